// round 9
// baseline (speedup 1.0000x reference)
#include <cuda_runtime.h>
#include <math_constants.h>

#define BB 2
#define NN 4096
#define DD 64
#define CMX 64
#define HH 8
#define KK 16
#define BN 8192            // BB*NN
#define NSPLIT 64          // wqk n-splits
#define FULLMASK 0xffffffffu

// ---------------- scratch (device globals; no allocation) ----------------
__device__ float4 g_p1[BN], g_p2[BN], g_p2w[BN];        // packed xyz + sqnorm
__device__ float  g_f1t[BN*DD], g_f2t[BN*DD];           // transposed features [B,N,D]
__device__ int    g_idxA[BN*KK], g_idxB[BN*KK], g_idxS[BN*KK];
__device__ float  g_part1[BN*CMX];                      // layer1 partial from f1 (+bias)
__device__ float  g_feat[BN*KK*CMX], g_featw[BN*KK*CMX];
__device__ float  g_wqkp[NSPLIT*BB*CMX*KK*KK];          // per-split partials (deterministic)
__device__ float  g_rsum[BB*CMX*KK], g_csum[BB*CMX*KK];
__device__ float  g_cost[BN*CMX], g_costw[BN*CMX];      // [b,n,c] layout

// ---------------- pack xyz -> float4(x,y,z,|p|^2) ----------------
__global__ void pack_xyz_k(const float* __restrict__ x1,
                           const float* __restrict__ x2,
                           const float* __restrict__ x2w) {
    int i = blockIdx.x * blockDim.x + threadIdx.x;
    if (i >= BN) return;
    int b = i >> 12, n = i & (NN - 1);
#pragma unroll
    for (int t = 0; t < 3; t++) {
        const float* s = (t == 0) ? x1 : (t == 1) ? x2 : x2w;
        float4* d      = (t == 0) ? g_p1 : (t == 1) ? g_p2 : g_p2w;
        float x = s[(size_t)b*3*NN + n];
        float y = s[(size_t)b*3*NN + NN + n];
        float z = s[(size_t)b*3*NN + 2*NN + n];
        d[i] = make_float4(x, y, z, x*x + y*y + z*z);
    }
}

// ---------------- transpose points [B,D,N] -> [B,N,D] ----------------
__global__ void transpose_k(const float* __restrict__ pA,
                            const float* __restrict__ pB) {
    __shared__ float t[32][33];
    int a = blockIdx.z >> 1;      // 0: points1, 1: points2
    int b = blockIdx.z & 1;
    const float* src = a ? pB : pA;
    float* dst       = a ? g_f2t : g_f1t;
    int n0 = blockIdx.x * 32, c0 = blockIdx.y * 32;
#pragma unroll
    for (int j = 0; j < 4; j++)
        t[threadIdx.y + 8*j][threadIdx.x] =
            src[((size_t)b*DD + c0 + threadIdx.y + 8*j)*NN + n0 + threadIdx.x];
    __syncthreads();
#pragma unroll
    for (int j = 0; j < 4; j++)
        dst[((size_t)b*NN + n0 + threadIdx.y + 8*j)*DD + c0 + threadIdx.x] =
            t[threadIdx.x][threadIdx.y + 8*j];
}

// ---------------- KNN body: warp-distributed top-16 in registers ----------------
__device__ __forceinline__ void knn_body(int which, int q) {
    const float4* ref = (which == 0) ? g_p2 : (which == 1) ? g_p2w : g_p1;
    int* outIdx       = (which == 0) ? g_idxA : (which == 1) ? g_idxB : g_idxS;
    int lane = threadIdx.x & 31;
    int b = q >> 12;
    const float4* refb = ref + b*NN;
    float4 Q = g_p1[q];

    float vd = CUDART_INF_F; int vi = 0x7fffffff;        // my slot of the distributed list
    float taud = CUDART_INF_F; int taui = 0x7fffffff;    // lane-15 entry (threshold)

#pragma unroll 4
    for (int j = 0; j < NN/32; j++) {
        int gi = j*32 + lane;
        float4 R = __ldg(&refb[gi]);
        float d = Q.w + R.w - 2.f*(Q.x*R.x + Q.y*R.y + Q.z*R.z);
        bool acc = (d < taud) || (d == taud && gi < taui);
        unsigned m = __ballot_sync(FULLMASK, acc);
        while (m) {
            int src = __ffs(m) - 1; m &= m - 1;
            float xd = __shfl_sync(FULLMASK, d,  src);
            int   xi = __shfl_sync(FULLMASK, gi, src);
            bool lt = (vd < xd) || (vd == xd && vi < xi);
            int pos = __popc(__ballot_sync(FULLMASK, lt) & 0xffffu);
            if (pos < 16) {
                float pd = __shfl_up_sync(FULLMASK, vd, 1);
                int   pi = __shfl_up_sync(FULLMASK, vi, 1);
                if (lane < 16) {
                    if (lane == pos)      { vd = xd; vi = xi; }
                    else if (lane > pos)  { vd = pd; vi = pi; }
                }
                taud = __shfl_sync(FULLMASK, vd, 15);
                taui = __shfl_sync(FULLMASK, vi, 15);
            }
        }
    }
    if (lane < 16) outIdx[q*KK + lane] = vi;
}

// ---------------- fused: knn A/B (y=0,1) + part1 (y=2) ----------------
__global__ __launch_bounds__(256) void knnAB_part1_k(const float* __restrict__ W0,
                                                     const float* __restrict__ b0) {
    __shared__ __align__(16) float w0s[64*68];
    __shared__ __align__(16) float buf[8][64];
    int w = threadIdx.x >> 5, lane = threadIdx.x & 31;

    if (blockIdx.y < 2) {
        knn_body(blockIdx.y, blockIdx.x * 8 + w);
        return;
    }
    // part1: one point per warp
    for (int t = threadIdx.x; t < 64*64; t += 256) {
        int o = t >> 6, c = t & 63;
        w0s[o*68 + c] = W0[o*131 + c];
    }
    __syncthreads();
    int i = blockIdx.x*8 + w;
    buf[w][lane]      = g_f1t[(size_t)i*64 + lane];
    buf[w][lane + 32] = g_f1t[(size_t)i*64 + 32 + lane];
    __syncwarp();
    float a0 = b0[lane], a1 = b0[lane + 32];
#pragma unroll
    for (int c4 = 0; c4 < 16; c4++) {
        float4 wa = *(const float4*)&w0s[lane*68 + c4*4];
        float4 wb = *(const float4*)&w0s[(lane+32)*68 + c4*4];
        float4 f  = *(const float4*)&buf[w][c4*4];
        a0 = fmaf(wa.x, f.x, a0); a0 = fmaf(wa.y, f.y, a0);
        a0 = fmaf(wa.z, f.z, a0); a0 = fmaf(wa.w, f.w, a0);
        a1 = fmaf(wb.x, f.x, a1); a1 = fmaf(wb.y, f.y, a1);
        a1 = fmaf(wb.z, f.z, a1); a1 = fmaf(wb.w, f.w, a1);
    }
    g_part1[(size_t)i*64 + lane]      = a0;
    g_part1[(size_t)i*64 + 32 + lane] = a1;
}

// ---------------- fused: MLP (blocks 0..1023) + knn-self (blocks 1024..2047) ----------------
__global__ __launch_bounds__(256) void mlp_knnS_k(const float* __restrict__ W0,
                                                  const float* __restrict__ W1,
                                                  const float* __restrict__ b1) {
    __shared__ __align__(16) float w0b[64*68];   // cols 64..130 of W0, padded stride 68
    __shared__ __align__(16) float w1s[64*68];   // W1, padded stride 68
    __shared__ float b1s[64];
    __shared__ __align__(16) float buf[8][4][68]; // activations; reused as mid
    int w = threadIdx.x >> 5, lane = threadIdx.x & 31;

    if (blockIdx.x >= 1024) {
        knn_body(2, (blockIdx.x - 1024) * 8 + w);
        return;
    }
    for (int t = threadIdx.x; t < 64*67; t += 256) {
        int o = t / 67, c = t % 67;
        w0b[o*68 + c] = W0[o*131 + 64 + c];
    }
    for (int t = threadIdx.x; t < 64*64; t += 256) {
        int o = t >> 6, c = t & 63;
        w1s[o*68 + c] = W1[t];
    }
    if (threadIdx.x < 64) b1s[threadIdx.x] = b1[threadIdx.x];
    __syncthreads();

    const int NG = BN * KK * 2 / 4;   // 65536 groups of 4 rows (32768 per array)
    for (int g = blockIdx.x*8 + w; g < NG; g += 1024*8) {
        int a   = g >> 15;               // 0: feat, 1: featw
        int rem = g & 32767;
        int i   = rem >> 2;              // 0..8191
        int kg  = (rem & 3) << 2;        // k base of this group
        int jg = 0;
        if (lane < 4) {
            int jl = (a ? g_idxB : g_idxA)[i*16 + kg + lane];
            jg = (i & ~(NN - 1)) + jl;
        }
        int jgr[4];
        jgr[0] = __shfl_sync(FULLMASK, jg, 0);
        jgr[1] = __shfl_sync(FULLMASK, jg, 1);
        jgr[2] = __shfl_sync(FULLMASK, jg, 2);
        jgr[3] = __shfl_sync(FULLMASK, jg, 3);
#pragma unroll
        for (int r = 0; r < 4; r++) {
            buf[w][r][lane]      = g_f2t[(size_t)jgr[r]*64 + lane];
            buf[w][r][lane + 32] = g_f2t[(size_t)jgr[r]*64 + 32 + lane];
        }
        if (lane < 4) {
            float4 Pr = a ? g_p2w[jg] : g_p2[jg];
            float4 Pq = g_p1[i];
            buf[w][lane][64] = Pr.x - Pq.x;
            buf[w][lane][65] = Pr.y - Pq.y;
            buf[w][lane][66] = Pr.z - Pq.z;
        }
        __syncwarp();
        float pa0 = g_part1[(size_t)i*64 + lane];
        float pa1 = g_part1[(size_t)i*64 + 32 + lane];
        float a0[4], a1[4];
#pragma unroll
        for (int r = 0; r < 4; r++) { a0[r] = pa0; a1[r] = pa1; }
#pragma unroll 4
        for (int c4 = 0; c4 < 16; c4++) {
            float4 wa = *(const float4*)&w0b[lane*68 + c4*4];
            float4 wb = *(const float4*)&w0b[(lane+32)*68 + c4*4];
#pragma unroll
            for (int r = 0; r < 4; r++) {
                float4 f = *(const float4*)&buf[w][r][c4*4];
                a0[r] = fmaf(wa.x, f.x, a0[r]); a0[r] = fmaf(wa.y, f.y, a0[r]);
                a0[r] = fmaf(wa.z, f.z, a0[r]); a0[r] = fmaf(wa.w, f.w, a0[r]);
                a1[r] = fmaf(wb.x, f.x, a1[r]); a1[r] = fmaf(wb.y, f.y, a1[r]);
                a1[r] = fmaf(wb.z, f.z, a1[r]); a1[r] = fmaf(wb.w, f.w, a1[r]);
            }
        }
#pragma unroll
        for (int c = 64; c < 67; c++) {
            float wa = w0b[lane*68 + c];
            float wb = w0b[(lane+32)*68 + c];
#pragma unroll
            for (int r = 0; r < 4; r++) {
                float f = buf[w][r][c];
                a0[r] = fmaf(wa, f, a0[r]);
                a1[r] = fmaf(wb, f, a1[r]);
            }
        }
        __syncwarp();                    // all reads of buf done; reuse as mid
#pragma unroll
        for (int r = 0; r < 4; r++) {
            a0[r] = a0[r] >= 0.f ? a0[r] : 0.1f*a0[r];
            a1[r] = a1[r] >= 0.f ? a1[r] : 0.1f*a1[r];
            buf[w][r][lane]      = a0[r];
            buf[w][r][lane + 32] = a1[r];
        }
        __syncwarp();
        float o0[4], o1[4];
#pragma unroll
        for (int r = 0; r < 4; r++) { o0[r] = b1s[lane]; o1[r] = b1s[lane + 32]; }
#pragma unroll 4
        for (int c4 = 0; c4 < 16; c4++) {
            float4 wa = *(const float4*)&w1s[lane*68 + c4*4];
            float4 wb = *(const float4*)&w1s[(lane+32)*68 + c4*4];
#pragma unroll
            for (int r = 0; r < 4; r++) {
                float4 f = *(const float4*)&buf[w][r][c4*4];
                o0[r] = fmaf(wa.x, f.x, o0[r]); o0[r] = fmaf(wa.y, f.y, o0[r]);
                o0[r] = fmaf(wa.z, f.z, o0[r]); o0[r] = fmaf(wa.w, f.w, o0[r]);
                o1[r] = fmaf(wb.x, f.x, o1[r]); o1[r] = fmaf(wb.y, f.y, o1[r]);
                o1[r] = fmaf(wb.z, f.z, o1[r]); o1[r] = fmaf(wb.w, f.w, o1[r]);
            }
        }
        float* dst = a ? g_featw : g_feat;
        size_t r2 = (size_t)i*16 + kg;
#pragma unroll
        for (int r = 0; r < 4; r++) {
            float v0 = o0[r] >= 0.f ? o0[r] : 0.1f*o0[r];
            float v1 = o1[r] >= 0.f ? o1[r] : 0.1f*o1[r];
            dst[(r2 + r)*64 + lane]      = v0;
            dst[(r2 + r)*64 + 32 + lane] = v1;
        }
        __syncwarp();
    }
}

// ---------------- wqk v2: block = (n-split of 64, b), ALL 64 channels per block ----------------
__global__ __launch_bounds__(256) void wqk_k() {
    __shared__ float fs[16][256];       // feat  [c in subtile][n*16+k]
    __shared__ float wsm[16][256];      // featw [c in subtile][n*16+l]
    int ns = blockIdx.x;                // 0..NSPLIT-1 (64 n each)
    int b  = blockIdx.y;
    int tid = threadIdx.x;
    int nl = tid >> 4, kl = tid & 15;   // load mapping
    int kc = tid >> 4, lc = tid & 15;   // compute mapping (k,l)

    float acc[64];
#pragma unroll
    for (int c = 0; c < 64; c++) acc[c] = 0.f;

    for (int ch = 0; ch < 4; ch++) {
        int n0 = ns*64 + ch*16;
        size_t rowf = ((size_t)(b*NN + n0 + nl)*16 + kl)*64;
#pragma unroll
        for (int cp = 0; cp < 4; cp++) {
            __syncthreads();
            const float4* fp = (const float4*)(g_feat  + rowf + cp*16);
            const float4* gp = (const float4*)(g_featw + rowf + cp*16);
            int base = nl*16 + kl;
#pragma unroll
            for (int v = 0; v < 4; v++) {
                float4 u = fp[v];
                fs[v*4+0][base] = u.x; fs[v*4+1][base] = u.y;
                fs[v*4+2][base] = u.z; fs[v*4+3][base] = u.w;
                float4 t = gp[v];
                wsm[v*4+0][base] = t.x; wsm[v*4+1][base] = t.y;
                wsm[v*4+2][base] = t.z; wsm[v*4+3][base] = t.w;
            }
            __syncthreads();
#pragma unroll 2
            for (int n = 0; n < 16; n++) {
                int bk = n*16 + kc, bl = n*16 + lc;
#pragma unroll
                for (int c = 0; c < 16; c++)
                    acc[cp*16 + c] = fmaf(fs[c][bk], wsm[c][bl], acc[cp*16 + c]);
            }
        }
    }
#pragma unroll
    for (int c = 0; c < 64; c++)
        g_wqkp[(((size_t)ns*BB + b)*CMX + c)*256 + kc*16 + lc] = acc[c];
}

// ---------------- softmax + clip + row/col sums ----------------
__global__ void softmax_k() {
    int t = blockIdx.x*256 + threadIdx.x;     // <<<8,256>>> -> 2048 threads
    int k  = t & 15;
    int bc = t >> 4;                          // 0..127 = b*64+c
    if (bc >= BB*CMX) return;
    int b = bc >> 6, c = bc & 63;
    const float inv_sqrt3 = 0.57735026918962576f;
    float row[16];
#pragma unroll
    for (int l = 0; l < 16; l++) {
        float s = 0.f;
        for (int sp = 0; sp < NSPLIT; sp++)
            s += g_wqkp[(((size_t)sp*BB + b)*CMX + c)*256 + k*16 + l];
        row[l] = s;
    }
    float m = row[0];
#pragma unroll
    for (int l = 1; l < 16; l++) m = fmaxf(m, row[l]);
    float sum = 0.f;
#pragma unroll
    for (int l = 0; l < 16; l++) { row[l] = expf(row[l] - m); sum += row[l]; }
    float inv = 1.f / sum;
    float rs = 0.f;
#pragma unroll
    for (int l = 0; l < 16; l++) {
        float v = fmaxf(row[l]*inv*inv_sqrt3, 1e-10f);
        rs += v; row[l] = v;
    }
    g_rsum[bc*16 + k] = rs;
#pragma unroll
    for (int l = 0; l < 16; l++) {
        float v = row[l];
        v += __shfl_xor_sync(0xffffffffu, v, 1);
        v += __shfl_xor_sync(0xffffffffu, v, 2);
        v += __shfl_xor_sync(0xffffffffu, v, 4);
        v += __shfl_xor_sync(0xffffffffu, v, 8);
        if (k == 0) g_csum[bc*16 + l] = v;
    }
}

// ---------------- cost/costw: [b,n,c] layout for coalesced gather later ----------------
__global__ __launch_bounds__(256) void cost_k() {
    int t = blockIdx.x*256 + threadIdx.x;    // BN*64 threads
    int i = t >> 6, c = t & 63;
    int b = i >> 12;
    const float* cs = &g_csum[(size_t)(b*64 + c)*16];
    const float* rs = &g_rsum[(size_t)(b*64 + c)*16];
    float a = 0.f, aw = 0.f;
#pragma unroll
    for (int l = 0; l < 16; l++) {
        a  = fmaf(g_feat [((size_t)i*16 + l)*64 + c], cs[l], a);
        aw = fmaf(g_featw[((size_t)i*16 + l)*64 + c], rs[l], aw);
    }
    g_cost[t] = a; g_costw[t] = aw;
}

// ---------------- WeightNet + gather + final contraction ----------------
__global__ __launch_bounds__(128) void final_k(
    const float* __restrict__ wW0, const float* __restrict__ wb0,
    const float* __restrict__ wg0, const float* __restrict__ wbe0,
    const float* __restrict__ wW1, const float* __restrict__ wb1,
    const float* __restrict__ wg1, const float* __restrict__ wbe1,
    const float* __restrict__ wW2, const float* __restrict__ wb2,
    const float* __restrict__ wg2, const float* __restrict__ wbe2,
    float* __restrict__ out) {
    __shared__ float grp[128*65];           // grouped rows, padded
    __shared__ float w0f[24], b0f[8], s0f[8], e0f[8];
    __shared__ float w1f[64], b1f[8], s1f[8], e1f[8];
    __shared__ float w2f[512], b2f[64], s2f[64], e2f[64];
    int tid = threadIdx.x;
    const float invs = 1.f / sqrtf(1.f + 1e-5f);
    if (tid < 24) w0f[tid] = wW0[tid];
    if (tid < 8) {
        b0f[tid] = wb0[tid]; s0f[tid] = wg0[tid]*invs; e0f[tid] = wbe0[tid];
        b1f[tid] = wb1[tid]; s1f[tid] = wg1[tid]*invs; e1f[tid] = wbe1[tid];
    }
    if (tid < 64) {
        w1f[tid] = wW1[tid];
        b2f[tid] = wb2[tid]; s2f[tid] = wg2[tid]*invs; e2f[tid] = wbe2[tid];
    }
    for (int t = tid; t < 512; t += 128) w2f[t] = wW2[t];

    int i0 = blockIdx.x * 8;
    int b = i0 >> 12;
    __syncthreads();
    for (int s = 0; s < 64; s++) {
        int e = s*128 + tid;
        int rowe = e >> 6, ce = e & 63;
        int ie = i0 + (rowe >> 4);
        int ke = rowe & 15;
        int je = g_idxS[ie*16 + ke];
        int jg = (b << 12) + je;
        grp[rowe*65 + ce] = g_cost[(size_t)jg*64 + ce] + g_costw[(size_t)jg*64 + ce];
    }
    __syncthreads();

    int nl = tid >> 4, k = tid & 15;
    int i = i0 + nl, n = i & (NN - 1);
    int j = g_idxS[i*16 + k];
    int jg = (b << 12) + j;
    float4 Pj = g_p1[jg], Pi = g_p1[i];
    float dx = Pj.x - Pi.x, dy = Pj.y - Pi.y, dz = Pj.z - Pi.z;
    float h0[8];
#pragma unroll
    for (int o = 0; o < 8; o++) {
        float z = b0f[o] + w0f[o*3]*dx + w0f[o*3+1]*dy + w0f[o*3+2]*dz;
        z = z*s0f[o] + e0f[o];
        h0[o] = fmaxf(z, 0.f);
    }
    float h1[8];
#pragma unroll
    for (int o = 0; o < 8; o++) {
        float z = b1f[o];
#pragma unroll
        for (int c = 0; c < 8; c++) z = fmaf(w1f[o*8 + c], h0[c], z);
        z = z*s1f[o] + e1f[o];
        h1[o] = fmaxf(z, 0.f);
    }
    int myrow = nl*16 + k;
    for (int c = 0; c < 64; c++) {
        float z = b2f[c];
#pragma unroll
        for (int o = 0; o < 8; o++) z = fmaf(w2f[c*8 + o], h1[o], z);
        z = fmaxf(z*s2f[c] + e2f[c], 0.f);
        float v = z * grp[myrow*65 + c];
        v += __shfl_xor_sync(0xffffffffu, v, 1);
        v += __shfl_xor_sync(0xffffffffu, v, 2);
        v += __shfl_xor_sync(0xffffffffu, v, 4);
        v += __shfl_xor_sync(0xffffffffu, v, 8);
        if (k == 0) out[((size_t)b*CMX + c)*NN + n] = v;
    }
}

// ---------------- launch ----------------
extern "C" void kernel_launch(void* const* d_in, const int* in_sizes, int n_in,
                              void* d_out, int out_size) {
    const float* xyz1    = (const float*)d_in[0];
    const float* xyz2    = (const float*)d_in[1];
    const float* xyz2w   = (const float*)d_in[2];
    const float* points1 = (const float*)d_in[3];
    const float* points2 = (const float*)d_in[4];
    const float* mlp_W0  = (const float*)d_in[5];
    const float* mlp_b0  = (const float*)d_in[6];
    const float* mlp_W1  = (const float*)d_in[7];
    const float* mlp_b1  = (const float*)d_in[8];
    const float* wn_W0   = (const float*)d_in[9];
    const float* wn_b0   = (const float*)d_in[10];
    const float* wn_g0   = (const float*)d_in[11];
    const float* wn_be0  = (const float*)d_in[12];
    const float* wn_W1   = (const float*)d_in[13];
    const float* wn_b1   = (const float*)d_in[14];
    const float* wn_g1   = (const float*)d_in[15];
    const float* wn_be1  = (const float*)d_in[16];
    const float* wn_W2   = (const float*)d_in[17];
    const float* wn_b2   = (const float*)d_in[18];
    const float* wn_g2   = (const float*)d_in[19];
    const float* wn_be2  = (const float*)d_in[20];
    float* out = (float*)d_out;

    pack_xyz_k<<<BN/256, 256>>>(xyz1, xyz2, xyz2w);
    transpose_k<<<dim3(NN/32, DD/32, 2*BB), dim3(32, 8)>>>(points1, points2);
    knnAB_part1_k<<<dim3(BN/8, 3), 256>>>(mlp_W0, mlp_b0);
    mlp_knnS_k<<<2048, 256>>>(mlp_W0, mlp_W1, mlp_b1);
    wqk_k<<<dim3(NSPLIT, BB), 256>>>();
    softmax_k<<<8, 256>>>();
    cost_k<<<BN*64/256, 256>>>();
    final_k<<<BN/8, 128>>>(wn_W0, wn_b0, wn_g0, wn_be0,
                           wn_W1, wn_b1, wn_g1, wn_be1,
                           wn_W2, wn_b2, wn_g2, wn_be2, out);
}

// round 11
// speedup vs baseline: 1.0345x; 1.0345x over previous
#include <cuda_runtime.h>
#include <math_constants.h>

#define BB 2
#define NN 4096
#define DD 64
#define CMX 64
#define HH 8
#define KK 16
#define BN 8192            // BB*NN
#define NSPLIT 64          // wqk n-splits
#define FULLMASK 0xffffffffu

// ---------------- scratch (device globals; no allocation) ----------------
__device__ float4 g_p1[BN], g_p2[BN], g_p2w[BN];        // packed xyz + sqnorm
__device__ float  g_f1t[BN*DD], g_f2t[BN*DD];           // transposed features [B,N,D]
__device__ int    g_idxA[BN*KK], g_idxB[BN*KK], g_idxS[BN*KK];
__device__ float  g_part1[BN*CMX];                      // layer1 partial from f1 (+bias)
__device__ float  g_feat[BN*KK*CMX], g_featw[BN*KK*CMX];
__device__ float  g_wqkp[NSPLIT*BB*CMX*KK*KK];          // per-split partials (deterministic)
__device__ float  g_rsum[BB*CMX*KK], g_csum[BB*CMX*KK];
__device__ float  g_cost[BN*CMX], g_costw[BN*CMX];      // [b,n,c] layout

// ---------------- pack xyz -> float4(x,y,z,|p|^2) ----------------
__global__ void pack_xyz_k(const float* __restrict__ x1,
                           const float* __restrict__ x2,
                           const float* __restrict__ x2w) {
    int i = blockIdx.x * blockDim.x + threadIdx.x;
    if (i >= BN) return;
    int b = i >> 12, n = i & (NN - 1);
#pragma unroll
    for (int t = 0; t < 3; t++) {
        const float* s = (t == 0) ? x1 : (t == 1) ? x2 : x2w;
        float4* d      = (t == 0) ? g_p1 : (t == 1) ? g_p2 : g_p2w;
        float x = s[(size_t)b*3*NN + n];
        float y = s[(size_t)b*3*NN + NN + n];
        float z = s[(size_t)b*3*NN + 2*NN + n];
        d[i] = make_float4(x, y, z, x*x + y*y + z*z);
    }
}

// ---------------- transpose points [B,D,N] -> [B,N,D] ----------------
__global__ void transpose_k(const float* __restrict__ pA,
                            const float* __restrict__ pB) {
    __shared__ float t[32][33];
    int a = blockIdx.z >> 1;      // 0: points1, 1: points2
    int b = blockIdx.z & 1;
    const float* src = a ? pB : pA;
    float* dst       = a ? g_f2t : g_f1t;
    int n0 = blockIdx.x * 32, c0 = blockIdx.y * 32;
#pragma unroll
    for (int j = 0; j < 4; j++)
        t[threadIdx.y + 8*j][threadIdx.x] =
            src[((size_t)b*DD + c0 + threadIdx.y + 8*j)*NN + n0 + threadIdx.x];
    __syncthreads();
#pragma unroll
    for (int j = 0; j < 4; j++)
        dst[((size_t)b*NN + n0 + threadIdx.y + 8*j)*DD + c0 + threadIdx.x] =
            t[threadIdx.x][threadIdx.y + 8*j];
}

// ---------------- KNN body: warp-distributed top-16 in registers ----------------
__device__ __forceinline__ void knn_body(int which, int q) {
    const float4* ref = (which == 0) ? g_p2 : (which == 1) ? g_p2w : g_p1;
    int* outIdx       = (which == 0) ? g_idxA : (which == 1) ? g_idxB : g_idxS;
    int lane = threadIdx.x & 31;
    int b = q >> 12;
    const float4* refb = ref + b*NN;
    float4 Q = g_p1[q];

    float vd = CUDART_INF_F; int vi = 0x7fffffff;        // my slot of the distributed list
    float taud = CUDART_INF_F; int taui = 0x7fffffff;    // lane-15 entry (threshold)

#pragma unroll 4
    for (int j = 0; j < NN/32; j++) {
        int gi = j*32 + lane;
        float4 R = __ldg(&refb[gi]);
        float d = Q.w + R.w - 2.f*(Q.x*R.x + Q.y*R.y + Q.z*R.z);
        bool acc = (d < taud) || (d == taud && gi < taui);
        unsigned m = __ballot_sync(FULLMASK, acc);
        while (m) {
            int src = __ffs(m) - 1; m &= m - 1;
            float xd = __shfl_sync(FULLMASK, d,  src);
            int   xi = __shfl_sync(FULLMASK, gi, src);
            bool lt = (vd < xd) || (vd == xd && vi < xi);
            int pos = __popc(__ballot_sync(FULLMASK, lt) & 0xffffu);
            if (pos < 16) {
                float pd = __shfl_up_sync(FULLMASK, vd, 1);
                int   pi = __shfl_up_sync(FULLMASK, vi, 1);
                if (lane < 16) {
                    if (lane == pos)      { vd = xd; vi = xi; }
                    else if (lane > pos)  { vd = pd; vi = pi; }
                }
                taud = __shfl_sync(FULLMASK, vd, 15);
                taui = __shfl_sync(FULLMASK, vi, 15);
            }
        }
    }
    if (lane < 16) outIdx[q*KK + lane] = vi;
}

// ---------------- fused: knn x3 (y=0,1,2) + part1 (y=3); 19KB smem doesn't bind ----------------
__global__ __launch_bounds__(256) void knn3_part1_k(const float* __restrict__ W0,
                                                    const float* __restrict__ b0) {
    __shared__ __align__(16) float w0s[64*68];
    __shared__ __align__(16) float buf[8][64];
    int w = threadIdx.x >> 5, lane = threadIdx.x & 31;

    if (blockIdx.y < 3) {
        knn_body(blockIdx.y, blockIdx.x * 8 + w);
        return;
    }
    // part1: one point per warp
    for (int t = threadIdx.x; t < 64*64; t += 256) {
        int o = t >> 6, c = t & 63;
        w0s[o*68 + c] = W0[o*131 + c];
    }
    __syncthreads();
    int i = blockIdx.x*8 + w;
    buf[w][lane]      = g_f1t[(size_t)i*64 + lane];
    buf[w][lane + 32] = g_f1t[(size_t)i*64 + 32 + lane];
    __syncwarp();
    float a0 = b0[lane], a1 = b0[lane + 32];
#pragma unroll
    for (int c4 = 0; c4 < 16; c4++) {
        float4 wa = *(const float4*)&w0s[lane*68 + c4*4];
        float4 wb = *(const float4*)&w0s[(lane+32)*68 + c4*4];
        float4 f  = *(const float4*)&buf[w][c4*4];
        a0 = fmaf(wa.x, f.x, a0); a0 = fmaf(wa.y, f.y, a0);
        a0 = fmaf(wa.z, f.z, a0); a0 = fmaf(wa.w, f.w, a0);
        a1 = fmaf(wb.x, f.x, a1); a1 = fmaf(wb.y, f.y, a1);
        a1 = fmaf(wb.z, f.z, a1); a1 = fmaf(wb.w, f.w, a1);
    }
    g_part1[(size_t)i*64 + lane]      = a0;
    g_part1[(size_t)i*64 + 32 + lane] = a1;
}

// ---------------- MLP v3 (standalone, round-8 form): row-blocked R=4, float4 smem loads ----------------
__global__ __launch_bounds__(256) void mlp_k(const float* __restrict__ W0,
                                             const float* __restrict__ W1,
                                             const float* __restrict__ b1) {
    __shared__ __align__(16) float w0b[64*68];   // cols 64..130 of W0, padded stride 68
    __shared__ __align__(16) float w1s[64*68];   // W1, padded stride 68
    __shared__ float b1s[64];
    __shared__ __align__(16) float buf[8][4][68]; // activations; reused as mid
    int w = threadIdx.x >> 5, lane = threadIdx.x & 31;
    for (int t = threadIdx.x; t < 64*67; t += 256) {
        int o = t / 67, c = t % 67;
        w0b[o*68 + c] = W0[o*131 + 64 + c];
    }
    for (int t = threadIdx.x; t < 64*64; t += 256) {
        int o = t >> 6, c = t & 63;
        w1s[o*68 + c] = W1[t];
    }
    if (threadIdx.x < 64) b1s[threadIdx.x] = b1[threadIdx.x];
    __syncthreads();

    const int NG = BN * KK * 2 / 4;   // 65536 groups of 4 rows (32768 per array)
    for (int g = blockIdx.x*8 + w; g < NG; g += gridDim.x*8) {
        int a   = g >> 15;               // 0: feat, 1: featw
        int rem = g & 32767;
        int i   = rem >> 2;              // 0..8191
        int kg  = (rem & 3) << 2;        // k base of this group
        int jg = 0;
        if (lane < 4) {
            int jl = (a ? g_idxB : g_idxA)[i*16 + kg + lane];
            jg = (i & ~(NN - 1)) + jl;
        }
        int jgr[4];
        jgr[0] = __shfl_sync(FULLMASK, jg, 0);
        jgr[1] = __shfl_sync(FULLMASK, jg, 1);
        jgr[2] = __shfl_sync(FULLMASK, jg, 2);
        jgr[3] = __shfl_sync(FULLMASK, jg, 3);
#pragma unroll
        for (int r = 0; r < 4; r++) {
            buf[w][r][lane]      = g_f2t[(size_t)jgr[r]*64 + lane];
            buf[w][r][lane + 32] = g_f2t[(size_t)jgr[r]*64 + 32 + lane];
        }
        if (lane < 4) {
            float4 Pr = a ? g_p2w[jg] : g_p2[jg];
            float4 Pq = g_p1[i];
            buf[w][lane][64] = Pr.x - Pq.x;
            buf[w][lane][65] = Pr.y - Pq.y;
            buf[w][lane][66] = Pr.z - Pq.z;
        }
        __syncwarp();
        float pa0 = g_part1[(size_t)i*64 + lane];
        float pa1 = g_part1[(size_t)i*64 + 32 + lane];
        float a0[4], a1[4];
#pragma unroll
        for (int r = 0; r < 4; r++) { a0[r] = pa0; a1[r] = pa1; }
#pragma unroll 4
        for (int c4 = 0; c4 < 16; c4++) {
            float4 wa = *(const float4*)&w0b[lane*68 + c4*4];
            float4 wb = *(const float4*)&w0b[(lane+32)*68 + c4*4];
#pragma unroll
            for (int r = 0; r < 4; r++) {
                float4 f = *(const float4*)&buf[w][r][c4*4];
                a0[r] = fmaf(wa.x, f.x, a0[r]); a0[r] = fmaf(wa.y, f.y, a0[r]);
                a0[r] = fmaf(wa.z, f.z, a0[r]); a0[r] = fmaf(wa.w, f.w, a0[r]);
                a1[r] = fmaf(wb.x, f.x, a1[r]); a1[r] = fmaf(wb.y, f.y, a1[r]);
                a1[r] = fmaf(wb.z, f.z, a1[r]); a1[r] = fmaf(wb.w, f.w, a1[r]);
            }
        }
#pragma unroll
        for (int c = 64; c < 67; c++) {
            float wa = w0b[lane*68 + c];
            float wb = w0b[(lane+32)*68 + c];
#pragma unroll
            for (int r = 0; r < 4; r++) {
                float f = buf[w][r][c];
                a0[r] = fmaf(wa, f, a0[r]);
                a1[r] = fmaf(wb, f, a1[r]);
            }
        }
        __syncwarp();                    // all reads of buf done; reuse as mid
#pragma unroll
        for (int r = 0; r < 4; r++) {
            a0[r] = a0[r] >= 0.f ? a0[r] : 0.1f*a0[r];
            a1[r] = a1[r] >= 0.f ? a1[r] : 0.1f*a1[r];
            buf[w][r][lane]      = a0[r];
            buf[w][r][lane + 32] = a1[r];
        }
        __syncwarp();
        float o0[4], o1[4];
#pragma unroll
        for (int r = 0; r < 4; r++) { o0[r] = b1s[lane]; o1[r] = b1s[lane + 32]; }
#pragma unroll 4
        for (int c4 = 0; c4 < 16; c4++) {
            float4 wa = *(const float4*)&w1s[lane*68 + c4*4];
            float4 wb = *(const float4*)&w1s[(lane+32)*68 + c4*4];
#pragma unroll
            for (int r = 0; r < 4; r++) {
                float4 f = *(const float4*)&buf[w][r][c4*4];
                o0[r] = fmaf(wa.x, f.x, o0[r]); o0[r] = fmaf(wa.y, f.y, o0[r]);
                o0[r] = fmaf(wa.z, f.z, o0[r]); o0[r] = fmaf(wa.w, f.w, o0[r]);
                o1[r] = fmaf(wb.x, f.x, o1[r]); o1[r] = fmaf(wb.y, f.y, o1[r]);
                o1[r] = fmaf(wb.z, f.z, o1[r]); o1[r] = fmaf(wb.w, f.w, o1[r]);
            }
        }
        float* dst = a ? g_featw : g_feat;
        size_t r2 = (size_t)i*16 + kg;
#pragma unroll
        for (int r = 0; r < 4; r++) {
            float v0 = o0[r] >= 0.f ? o0[r] : 0.1f*o0[r];
            float v1 = o1[r] >= 0.f ? o1[r] : 0.1f*o1[r];
            dst[(r2 + r)*64 + lane]      = v0;
            dst[(r2 + r)*64 + 32 + lane] = v1;
        }
        __syncwarp();
    }
}

// ---------------- wqk v2: block = (n-split of 64, b), ALL 64 channels per block ----------------
__global__ __launch_bounds__(256) void wqk_k() {
    __shared__ float fs[16][256];       // feat  [c in subtile][n*16+k]
    __shared__ float wsm[16][256];      // featw [c in subtile][n*16+l]
    int ns = blockIdx.x;                // 0..NSPLIT-1 (64 n each)
    int b  = blockIdx.y;
    int tid = threadIdx.x;
    int nl = tid >> 4, kl = tid & 15;   // load mapping
    int kc = tid >> 4, lc = tid & 15;   // compute mapping (k,l)

    float acc[64];
#pragma unroll
    for (int c = 0; c < 64; c++) acc[c] = 0.f;

    for (int ch = 0; ch < 4; ch++) {
        int n0 = ns*64 + ch*16;
        size_t rowf = ((size_t)(b*NN + n0 + nl)*16 + kl)*64;
#pragma unroll
        for (int cp = 0; cp < 4; cp++) {
            __syncthreads();
            const float4* fp = (const float4*)(g_feat  + rowf + cp*16);
            const float4* gp = (const float4*)(g_featw + rowf + cp*16);
            int base = nl*16 + kl;
#pragma unroll
            for (int v = 0; v < 4; v++) {
                float4 u = fp[v];
                fs[v*4+0][base] = u.x; fs[v*4+1][base] = u.y;
                fs[v*4+2][base] = u.z; fs[v*4+3][base] = u.w;
                float4 t = gp[v];
                wsm[v*4+0][base] = t.x; wsm[v*4+1][base] = t.y;
                wsm[v*4+2][base] = t.z; wsm[v*4+3][base] = t.w;
            }
            __syncthreads();
#pragma unroll 2
            for (int n = 0; n < 16; n++) {
                int bk = n*16 + kc, bl = n*16 + lc;
#pragma unroll
                for (int c = 0; c < 16; c++)
                    acc[cp*16 + c] = fmaf(fs[c][bk], wsm[c][bl], acc[cp*16 + c]);
            }
        }
    }
#pragma unroll
    for (int c = 0; c < 64; c++)
        g_wqkp[(((size_t)ns*BB + b)*CMX + c)*256 + kc*16 + lc] = acc[c];
}

// ---------------- softmax + clip + row/col sums ----------------
__global__ void softmax_k() {
    int t = blockIdx.x*256 + threadIdx.x;     // <<<8,256>>> -> 2048 threads
    int k  = t & 15;
    int bc = t >> 4;                          // 0..127 = b*64+c
    if (bc >= BB*CMX) return;
    int b = bc >> 6, c = bc & 63;
    const float inv_sqrt3 = 0.57735026918962576f;
    float row[16];
#pragma unroll
    for (int l = 0; l < 16; l++) {
        float s = 0.f;
        for (int sp = 0; sp < NSPLIT; sp++)
            s += g_wqkp[(((size_t)sp*BB + b)*CMX + c)*256 + k*16 + l];
        row[l] = s;
    }
    float m = row[0];
#pragma unroll
    for (int l = 1; l < 16; l++) m = fmaxf(m, row[l]);
    float sum = 0.f;
#pragma unroll
    for (int l = 0; l < 16; l++) { row[l] = expf(row[l] - m); sum += row[l]; }
    float inv = 1.f / sum;
    float rs = 0.f;
#pragma unroll
    for (int l = 0; l < 16; l++) {
        float v = fmaxf(row[l]*inv*inv_sqrt3, 1e-10f);
        rs += v; row[l] = v;
    }
    g_rsum[bc*16 + k] = rs;
#pragma unroll
    for (int l = 0; l < 16; l++) {
        float v = row[l];
        v += __shfl_xor_sync(0xffffffffu, v, 1);
        v += __shfl_xor_sync(0xffffffffu, v, 2);
        v += __shfl_xor_sync(0xffffffffu, v, 4);
        v += __shfl_xor_sync(0xffffffffu, v, 8);
        if (k == 0) g_csum[bc*16 + l] = v;
    }
}

// ---------------- cost/costw: [b,n,c] layout for coalesced gather later ----------------
__global__ __launch_bounds__(256) void cost_k() {
    int t = blockIdx.x*256 + threadIdx.x;    // BN*64 threads
    int i = t >> 6, c = t & 63;
    int b = i >> 12;
    const float* cs = &g_csum[(size_t)(b*64 + c)*16];
    const float* rs = &g_rsum[(size_t)(b*64 + c)*16];
    float a = 0.f, aw = 0.f;
#pragma unroll
    for (int l = 0; l < 16; l++) {
        a  = fmaf(g_feat [((size_t)i*16 + l)*64 + c], cs[l], a);
        aw = fmaf(g_featw[((size_t)i*16 + l)*64 + c], rs[l], aw);
    }
    g_cost[t] = a; g_costw[t] = aw;
}

// ---------------- WeightNet + gather + final contraction ----------------
__global__ __launch_bounds__(128) void final_k(
    const float* __restrict__ wW0, const float* __restrict__ wb0,
    const float* __restrict__ wg0, const float* __restrict__ wbe0,
    const float* __restrict__ wW1, const float* __restrict__ wb1,
    const float* __restrict__ wg1, const float* __restrict__ wbe1,
    const float* __restrict__ wW2, const float* __restrict__ wb2,
    const float* __restrict__ wg2, const float* __restrict__ wbe2,
    float* __restrict__ out) {
    __shared__ float grp[128*65];           // grouped rows, padded
    __shared__ float w0f[24], b0f[8], s0f[8], e0f[8];
    __shared__ float w1f[64], b1f[8], s1f[8], e1f[8];
    __shared__ float w2f[512], b2f[64], s2f[64], e2f[64];
    int tid = threadIdx.x;
    const float invs = 1.f / sqrtf(1.f + 1e-5f);
    if (tid < 24) w0f[tid] = wW0[tid];
    if (tid < 8) {
        b0f[tid] = wb0[tid]; s0f[tid] = wg0[tid]*invs; e0f[tid] = wbe0[tid];
        b1f[tid] = wb1[tid]; s1f[tid] = wg1[tid]*invs; e1f[tid] = wbe1[tid];
    }
    if (tid < 64) {
        w1f[tid] = wW1[tid];
        b2f[tid] = wb2[tid]; s2f[tid] = wg2[tid]*invs; e2f[tid] = wbe2[tid];
    }
    for (int t = tid; t < 512; t += 128) w2f[t] = wW2[t];

    int i0 = blockIdx.x * 8;
    int b = i0 >> 12;
    __syncthreads();
    for (int s = 0; s < 64; s++) {
        int e = s*128 + tid;
        int rowe = e >> 6, ce = e & 63;
        int ie = i0 + (rowe >> 4);
        int ke = rowe & 15;
        int je = g_idxS[ie*16 + ke];
        int jg = (b << 12) + je;
        grp[rowe*65 + ce] = g_cost[(size_t)jg*64 + ce] + g_costw[(size_t)jg*64 + ce];
    }
    __syncthreads();

    int nl = tid >> 4, k = tid & 15;
    int i = i0 + nl, n = i & (NN - 1);
    int j = g_idxS[i*16 + k];
    int jg = (b << 12) + j;
    float4 Pj = g_p1[jg], Pi = g_p1[i];
    float dx = Pj.x - Pi.x, dy = Pj.y - Pi.y, dz = Pj.z - Pi.z;
    float h0[8];
#pragma unroll
    for (int o = 0; o < 8; o++) {
        float z = b0f[o] + w0f[o*3]*dx + w0f[o*3+1]*dy + w0f[o*3+2]*dz;
        z = z*s0f[o] + e0f[o];
        h0[o] = fmaxf(z, 0.f);
    }
    float h1[8];
#pragma unroll
    for (int o = 0; o < 8; o++) {
        float z = b1f[o];
#pragma unroll
        for (int c = 0; c < 8; c++) z = fmaf(w1f[o*8 + c], h0[c], z);
        z = z*s1f[o] + e1f[o];
        h1[o] = fmaxf(z, 0.f);
    }
    int myrow = nl*16 + k;
    for (int c = 0; c < 64; c++) {
        float z = b2f[c];
#pragma unroll
        for (int o = 0; o < 8; o++) z = fmaf(w2f[c*8 + o], h1[o], z);
        z = fmaxf(z*s2f[c] + e2f[c], 0.f);
        float v = z * grp[myrow*65 + c];
        v += __shfl_xor_sync(0xffffffffu, v, 1);
        v += __shfl_xor_sync(0xffffffffu, v, 2);
        v += __shfl_xor_sync(0xffffffffu, v, 4);
        v += __shfl_xor_sync(0xffffffffu, v, 8);
        if (k == 0) out[((size_t)b*CMX + c)*NN + n] = v;
    }
}

// ---------------- launch ----------------
extern "C" void kernel_launch(void* const* d_in, const int* in_sizes, int n_in,
                              void* d_out, int out_size) {
    const float* xyz1    = (const float*)d_in[0];
    const float* xyz2    = (const float*)d_in[1];
    const float* xyz2w   = (const float*)d_in[2];
    const float* points1 = (const float*)d_in[3];
    const float* points2 = (const float*)d_in[4];
    const float* mlp_W0  = (const float*)d_in[5];
    const float* mlp_b0  = (const float*)d_in[6];
    const float* mlp_W1  = (const float*)d_in[7];
    const float* mlp_b1  = (const float*)d_in[8];
    const float* wn_W0   = (const float*)d_in[9];
    const float* wn_b0   = (const float*)d_in[10];
    const float* wn_g0   = (const float*)d_in[11];
    const float* wn_be0  = (const float*)d_in[12];
    const float* wn_W1   = (const float*)d_in[13];
    const float* wn_b1   = (const float*)d_in[14];
    const float* wn_g1   = (const float*)d_in[15];
    const float* wn_be1  = (const float*)d_in[16];
    const float* wn_W2   = (const float*)d_in[17];
    const float* wn_b2   = (const float*)d_in[18];
    const float* wn_g2   = (const float*)d_in[19];
    const float* wn_be2  = (const float*)d_in[20];
    float* out = (float*)d_out;

    pack_xyz_k<<<BN/256, 256>>>(xyz1, xyz2, xyz2w);
    transpose_k<<<dim3(NN/32, DD/32, 2*BB), dim3(32, 8)>>>(points1, points2);
    knn3_part1_k<<<dim3(BN/8, 4), 256>>>(mlp_W0, mlp_b0);
    mlp_k<<<1024, 256>>>(mlp_W0, mlp_W1, mlp_b1);
    wqk_k<<<dim3(NSPLIT, BB), 256>>>();
    softmax_k<<<8, 256>>>();
    cost_k<<<BN*64/256, 256>>>();
    final_k<<<BN/8, 128>>>(wn_W0, wn_b0, wn_g0, wn_be0,
                           wn_W1, wn_b1, wn_g1, wn_be1,
                           wn_W2, wn_b2, wn_g2, wn_be2, out);
}

// round 12
// speedup vs baseline: 1.0778x; 1.0419x over previous
#include <cuda_runtime.h>
#include <math_constants.h>

#define BB 2
#define NN 4096
#define DD 64
#define CMX 64
#define HH 8
#define KK 16
#define BN 8192            // BB*NN
#define NSPLIT 64          // wqk n-splits
#define FULLMASK 0xffffffffu

// ---------------- scratch (device globals; no allocation) ----------------
__device__ float4 g_p1[BN], g_p2[BN], g_p2w[BN];        // packed xyz + sqnorm
__device__ float  g_f1t[BN*DD], g_f2t[BN*DD];           // transposed features [B,N,D]
__device__ int    g_idxA[BN*KK], g_idxB[BN*KK], g_idxS[BN*KK];
__device__ float  g_part1[BN*CMX];                      // layer1 partial from f1 (+bias)
__device__ float  g_feat[BN*KK*CMX], g_featw[BN*KK*CMX];
__device__ float  g_wqkp[NSPLIT*BB*CMX*KK*KK];          // per-split partials (deterministic)
__device__ float  g_rsum[BB*CMX*KK], g_csum[BB*CMX*KK];
__device__ float  g_cost[BN*CMX], g_costw[BN*CMX];      // [b,n,c] layout

// ---------------- pack xyz -> float4(x,y,z,|p|^2) ----------------
__global__ void pack_xyz_k(const float* __restrict__ x1,
                           const float* __restrict__ x2,
                           const float* __restrict__ x2w) {
    int i = blockIdx.x * blockDim.x + threadIdx.x;
    if (i >= BN) return;
    int b = i >> 12, n = i & (NN - 1);
#pragma unroll
    for (int t = 0; t < 3; t++) {
        const float* s = (t == 0) ? x1 : (t == 1) ? x2 : x2w;
        float4* d      = (t == 0) ? g_p1 : (t == 1) ? g_p2 : g_p2w;
        float x = s[(size_t)b*3*NN + n];
        float y = s[(size_t)b*3*NN + NN + n];
        float z = s[(size_t)b*3*NN + 2*NN + n];
        d[i] = make_float4(x, y, z, x*x + y*y + z*z);
    }
}

// ---------------- transpose points [B,D,N] -> [B,N,D] ----------------
__global__ void transpose_k(const float* __restrict__ pA,
                            const float* __restrict__ pB) {
    __shared__ float t[32][33];
    int a = blockIdx.z >> 1;      // 0: points1, 1: points2
    int b = blockIdx.z & 1;
    const float* src = a ? pB : pA;
    float* dst       = a ? g_f2t : g_f1t;
    int n0 = blockIdx.x * 32, c0 = blockIdx.y * 32;
#pragma unroll
    for (int j = 0; j < 4; j++)
        t[threadIdx.y + 8*j][threadIdx.x] =
            src[((size_t)b*DD + c0 + threadIdx.y + 8*j)*NN + n0 + threadIdx.x];
    __syncthreads();
#pragma unroll
    for (int j = 0; j < 4; j++)
        dst[((size_t)b*NN + n0 + threadIdx.y + 8*j)*DD + c0 + threadIdx.x] =
            t[threadIdx.x][threadIdx.y + 8*j];
}

// ---------------- KNN body: warp-distributed top-16 in registers ----------------
__device__ __forceinline__ void knn_body(int which, int q) {
    const float4* ref = (which == 0) ? g_p2 : (which == 1) ? g_p2w : g_p1;
    int* outIdx       = (which == 0) ? g_idxA : (which == 1) ? g_idxB : g_idxS;
    int lane = threadIdx.x & 31;
    int b = q >> 12;
    const float4* refb = ref + b*NN;
    float4 Q = g_p1[q];

    float vd = CUDART_INF_F; int vi = 0x7fffffff;        // my slot of the distributed list
    float taud = CUDART_INF_F; int taui = 0x7fffffff;    // lane-15 entry (threshold)

#pragma unroll 4
    for (int j = 0; j < NN/32; j++) {
        int gi = j*32 + lane;
        float4 R = __ldg(&refb[gi]);
        float d = Q.w + R.w - 2.f*(Q.x*R.x + Q.y*R.y + Q.z*R.z);
        bool acc = (d < taud) || (d == taud && gi < taui);
        unsigned m = __ballot_sync(FULLMASK, acc);
        while (m) {
            int src = __ffs(m) - 1; m &= m - 1;
            float xd = __shfl_sync(FULLMASK, d,  src);
            int   xi = __shfl_sync(FULLMASK, gi, src);
            bool lt = (vd < xd) || (vd == xd && vi < xi);
            int pos = __popc(__ballot_sync(FULLMASK, lt) & 0xffffu);
            if (pos < 16) {
                float pd = __shfl_up_sync(FULLMASK, vd, 1);
                int   pi = __shfl_up_sync(FULLMASK, vi, 1);
                if (lane < 16) {
                    if (lane == pos)      { vd = xd; vi = xi; }
                    else if (lane > pos)  { vd = pd; vi = pi; }
                }
                taud = __shfl_sync(FULLMASK, vd, 15);
                taui = __shfl_sync(FULLMASK, vi, 15);
            }
        }
    }
    if (lane < 16) outIdx[q*KK + lane] = vi;
}

// ---------------- fused: knn x3 (y=0,1,2) + part1 (y=3); 19KB smem doesn't bind ----------------
__global__ __launch_bounds__(256) void knn3_part1_k(const float* __restrict__ W0,
                                                    const float* __restrict__ b0) {
    __shared__ __align__(16) float w0s[64*68];
    __shared__ __align__(16) float buf[8][64];
    int w = threadIdx.x >> 5, lane = threadIdx.x & 31;

    if (blockIdx.y < 3) {
        knn_body(blockIdx.y, blockIdx.x * 8 + w);
        return;
    }
    // part1: one point per warp
    for (int t = threadIdx.x; t < 64*64; t += 256) {
        int o = t >> 6, c = t & 63;
        w0s[o*68 + c] = W0[o*131 + c];
    }
    __syncthreads();
    int i = blockIdx.x*8 + w;
    buf[w][lane]      = g_f1t[(size_t)i*64 + lane];
    buf[w][lane + 32] = g_f1t[(size_t)i*64 + 32 + lane];
    __syncwarp();
    float a0 = b0[lane], a1 = b0[lane + 32];
#pragma unroll
    for (int c4 = 0; c4 < 16; c4++) {
        float4 wa = *(const float4*)&w0s[lane*68 + c4*4];
        float4 wb = *(const float4*)&w0s[(lane+32)*68 + c4*4];
        float4 f  = *(const float4*)&buf[w][c4*4];
        a0 = fmaf(wa.x, f.x, a0); a0 = fmaf(wa.y, f.y, a0);
        a0 = fmaf(wa.z, f.z, a0); a0 = fmaf(wa.w, f.w, a0);
        a1 = fmaf(wb.x, f.x, a1); a1 = fmaf(wb.y, f.y, a1);
        a1 = fmaf(wb.z, f.z, a1); a1 = fmaf(wb.w, f.w, a1);
    }
    g_part1[(size_t)i*64 + lane]      = a0;
    g_part1[(size_t)i*64 + 32 + lane] = a1;
}

// ---------------- MLP v4: row-blocked R=8, 4 warps/block (weight-LDS bytes halved) ----------------
__global__ __launch_bounds__(128) void mlp_k(const float* __restrict__ W0,
                                             const float* __restrict__ W1,
                                             const float* __restrict__ b1) {
    __shared__ __align__(16) float w0b[64*68];   // cols 64..130 of W0, padded stride 68: 17408B
    __shared__ __align__(16) float w1s[64*68];   // W1, padded stride 68: 17408B
    __shared__ float b1s[64];                    // 256B
    __shared__ __align__(16) float buf[4][8][68]; // 8704B; reused as mid  (total 43776B)
    int w = threadIdx.x >> 5, lane = threadIdx.x & 31;
    for (int t = threadIdx.x; t < 64*67; t += 128) {
        int o = t / 67, c = t % 67;
        w0b[o*68 + c] = W0[o*131 + 64 + c];
    }
    for (int t = threadIdx.x; t < 64*64; t += 128) {
        int o = t >> 6, c = t & 63;
        w1s[o*68 + c] = W1[t];
    }
    if (threadIdx.x < 64) b1s[threadIdx.x] = b1[threadIdx.x];
    __syncthreads();

    const int NG = BN * KK * 2 / 8;   // 32768 groups of 8 rows (16384 per array)
    for (int g = blockIdx.x*4 + w; g < NG; g += gridDim.x*4) {
        int a   = g >> 14;               // 0: feat, 1: featw
        int rem = g & 16383;
        int i   = rem >> 1;              // 0..8191
        int kg  = (rem & 1) << 3;        // k base of this group (0 or 8)
        int jg = 0;
        if (lane < 8) {
            int jl = (a ? g_idxB : g_idxA)[i*16 + kg + lane];
            jg = (i & ~(NN - 1)) + jl;
        }
        int jgr[8];
#pragma unroll
        for (int r = 0; r < 8; r++) jgr[r] = __shfl_sync(FULLMASK, jg, r);
#pragma unroll
        for (int r = 0; r < 8; r++) {
            buf[w][r][lane]      = g_f2t[(size_t)jgr[r]*64 + lane];
            buf[w][r][lane + 32] = g_f2t[(size_t)jgr[r]*64 + 32 + lane];
        }
        if (lane < 8) {
            float4 Pr = a ? g_p2w[jg] : g_p2[jg];
            float4 Pq = g_p1[i];
            buf[w][lane][64] = Pr.x - Pq.x;
            buf[w][lane][65] = Pr.y - Pq.y;
            buf[w][lane][66] = Pr.z - Pq.z;
        }
        __syncwarp();
        float pa0 = g_part1[(size_t)i*64 + lane];
        float pa1 = g_part1[(size_t)i*64 + 32 + lane];
        float a0[8], a1[8];
#pragma unroll
        for (int r = 0; r < 8; r++) { a0[r] = pa0; a1[r] = pa1; }
#pragma unroll 4
        for (int c4 = 0; c4 < 16; c4++) {
            float4 wa = *(const float4*)&w0b[lane*68 + c4*4];
            float4 wb = *(const float4*)&w0b[(lane+32)*68 + c4*4];
#pragma unroll
            for (int r = 0; r < 8; r++) {
                float4 f = *(const float4*)&buf[w][r][c4*4];
                a0[r] = fmaf(wa.x, f.x, a0[r]); a0[r] = fmaf(wa.y, f.y, a0[r]);
                a0[r] = fmaf(wa.z, f.z, a0[r]); a0[r] = fmaf(wa.w, f.w, a0[r]);
                a1[r] = fmaf(wb.x, f.x, a1[r]); a1[r] = fmaf(wb.y, f.y, a1[r]);
                a1[r] = fmaf(wb.z, f.z, a1[r]); a1[r] = fmaf(wb.w, f.w, a1[r]);
            }
        }
#pragma unroll
        for (int c = 64; c < 67; c++) {
            float wa = w0b[lane*68 + c];
            float wb = w0b[(lane+32)*68 + c];
#pragma unroll
            for (int r = 0; r < 8; r++) {
                float f = buf[w][r][c];
                a0[r] = fmaf(wa, f, a0[r]);
                a1[r] = fmaf(wb, f, a1[r]);
            }
        }
        __syncwarp();                    // all reads of buf done; reuse as mid
#pragma unroll
        for (int r = 0; r < 8; r++) {
            a0[r] = a0[r] >= 0.f ? a0[r] : 0.1f*a0[r];
            a1[r] = a1[r] >= 0.f ? a1[r] : 0.1f*a1[r];
            buf[w][r][lane]      = a0[r];
            buf[w][r][lane + 32] = a1[r];
        }
        __syncwarp();
        float o0[8], o1[8];
#pragma unroll
        for (int r = 0; r < 8; r++) { o0[r] = b1s[lane]; o1[r] = b1s[lane + 32]; }
#pragma unroll 4
        for (int c4 = 0; c4 < 16; c4++) {
            float4 wa = *(const float4*)&w1s[lane*68 + c4*4];
            float4 wb = *(const float4*)&w1s[(lane+32)*68 + c4*4];
#pragma unroll
            for (int r = 0; r < 8; r++) {
                float4 f = *(const float4*)&buf[w][r][c4*4];
                o0[r] = fmaf(wa.x, f.x, o0[r]); o0[r] = fmaf(wa.y, f.y, o0[r]);
                o0[r] = fmaf(wa.z, f.z, o0[r]); o0[r] = fmaf(wa.w, f.w, o0[r]);
                o1[r] = fmaf(wb.x, f.x, o1[r]); o1[r] = fmaf(wb.y, f.y, o1[r]);
                o1[r] = fmaf(wb.z, f.z, o1[r]); o1[r] = fmaf(wb.w, f.w, o1[r]);
            }
        }
        float* dst = a ? g_featw : g_feat;
        size_t r2 = (size_t)i*16 + kg;
#pragma unroll
        for (int r = 0; r < 8; r++) {
            float v0 = o0[r] >= 0.f ? o0[r] : 0.1f*o0[r];
            float v1 = o1[r] >= 0.f ? o1[r] : 0.1f*o1[r];
            dst[(r2 + r)*64 + lane]      = v0;
            dst[(r2 + r)*64 + 32 + lane] = v1;
        }
        __syncwarp();
    }
}

// ---------------- wqk v2: block = (n-split of 64, b), ALL 64 channels per block ----------------
__global__ __launch_bounds__(256) void wqk_k() {
    __shared__ float fs[16][256];       // feat  [c in subtile][n*16+k]
    __shared__ float wsm[16][256];      // featw [c in subtile][n*16+l]
    int ns = blockIdx.x;                // 0..NSPLIT-1 (64 n each)
    int b  = blockIdx.y;
    int tid = threadIdx.x;
    int nl = tid >> 4, kl = tid & 15;   // load mapping
    int kc = tid >> 4, lc = tid & 15;   // compute mapping (k,l)

    float acc[64];
#pragma unroll
    for (int c = 0; c < 64; c++) acc[c] = 0.f;

    for (int ch = 0; ch < 4; ch++) {
        int n0 = ns*64 + ch*16;
        size_t rowf = ((size_t)(b*NN + n0 + nl)*16 + kl)*64;
#pragma unroll
        for (int cp = 0; cp < 4; cp++) {
            __syncthreads();
            const float4* fp = (const float4*)(g_feat  + rowf + cp*16);
            const float4* gp = (const float4*)(g_featw + rowf + cp*16);
            int base = nl*16 + kl;
#pragma unroll
            for (int v = 0; v < 4; v++) {
                float4 u = fp[v];
                fs[v*4+0][base] = u.x; fs[v*4+1][base] = u.y;
                fs[v*4+2][base] = u.z; fs[v*4+3][base] = u.w;
                float4 t = gp[v];
                wsm[v*4+0][base] = t.x; wsm[v*4+1][base] = t.y;
                wsm[v*4+2][base] = t.z; wsm[v*4+3][base] = t.w;
            }
            __syncthreads();
#pragma unroll 2
            for (int n = 0; n < 16; n++) {
                int bk = n*16 + kc, bl = n*16 + lc;
#pragma unroll
                for (int c = 0; c < 16; c++)
                    acc[cp*16 + c] = fmaf(fs[c][bk], wsm[c][bl], acc[cp*16 + c]);
            }
        }
    }
#pragma unroll
    for (int c = 0; c < 64; c++)
        g_wqkp[(((size_t)ns*BB + b)*CMX + c)*256 + kc*16 + lc] = acc[c];
}

// ---------------- softmax + clip + row/col sums ----------------
__global__ void softmax_k() {
    int t = blockIdx.x*256 + threadIdx.x;     // <<<8,256>>> -> 2048 threads
    int k  = t & 15;
    int bc = t >> 4;                          // 0..127 = b*64+c
    if (bc >= BB*CMX) return;
    int b = bc >> 6, c = bc & 63;
    const float inv_sqrt3 = 0.57735026918962576f;
    float row[16];
#pragma unroll
    for (int l = 0; l < 16; l++) {
        float s = 0.f;
        for (int sp = 0; sp < NSPLIT; sp++)
            s += g_wqkp[(((size_t)sp*BB + b)*CMX + c)*256 + k*16 + l];
        row[l] = s;
    }
    float m = row[0];
#pragma unroll
    for (int l = 1; l < 16; l++) m = fmaxf(m, row[l]);
    float sum = 0.f;
#pragma unroll
    for (int l = 0; l < 16; l++) { row[l] = expf(row[l] - m); sum += row[l]; }
    float inv = 1.f / sum;
    float rs = 0.f;
#pragma unroll
    for (int l = 0; l < 16; l++) {
        float v = fmaxf(row[l]*inv*inv_sqrt3, 1e-10f);
        rs += v; row[l] = v;
    }
    g_rsum[bc*16 + k] = rs;
#pragma unroll
    for (int l = 0; l < 16; l++) {
        float v = row[l];
        v += __shfl_xor_sync(0xffffffffu, v, 1);
        v += __shfl_xor_sync(0xffffffffu, v, 2);
        v += __shfl_xor_sync(0xffffffffu, v, 4);
        v += __shfl_xor_sync(0xffffffffu, v, 8);
        if (k == 0) g_csum[bc*16 + l] = v;
    }
}

// ---------------- cost/costw: [b,n,c] layout for coalesced gather later ----------------
__global__ __launch_bounds__(256) void cost_k() {
    int t = blockIdx.x*256 + threadIdx.x;    // BN*64 threads
    int i = t >> 6, c = t & 63;
    int b = i >> 12;
    const float* cs = &g_csum[(size_t)(b*64 + c)*16];
    const float* rs = &g_rsum[(size_t)(b*64 + c)*16];
    float a = 0.f, aw = 0.f;
#pragma unroll
    for (int l = 0; l < 16; l++) {
        a  = fmaf(g_feat [((size_t)i*16 + l)*64 + c], cs[l], a);
        aw = fmaf(g_featw[((size_t)i*16 + l)*64 + c], rs[l], aw);
    }
    g_cost[t] = a; g_costw[t] = aw;
}

// ---------------- WeightNet + gather + final contraction ----------------
__global__ __launch_bounds__(128) void final_k(
    const float* __restrict__ wW0, const float* __restrict__ wb0,
    const float* __restrict__ wg0, const float* __restrict__ wbe0,
    const float* __restrict__ wW1, const float* __restrict__ wb1,
    const float* __restrict__ wg1, const float* __restrict__ wbe1,
    const float* __restrict__ wW2, const float* __restrict__ wb2,
    const float* __restrict__ wg2, const float* __restrict__ wbe2,
    float* __restrict__ out) {
    __shared__ float grp[128*65];           // grouped rows, padded
    __shared__ float w0f[24], b0f[8], s0f[8], e0f[8];
    __shared__ float w1f[64], b1f[8], s1f[8], e1f[8];
    __shared__ float w2f[512], b2f[64], s2f[64], e2f[64];
    int tid = threadIdx.x;
    const float invs = 1.f / sqrtf(1.f + 1e-5f);
    if (tid < 24) w0f[tid] = wW0[tid];
    if (tid < 8) {
        b0f[tid] = wb0[tid]; s0f[tid] = wg0[tid]*invs; e0f[tid] = wbe0[tid];
        b1f[tid] = wb1[tid]; s1f[tid] = wg1[tid]*invs; e1f[tid] = wbe1[tid];
    }
    if (tid < 64) {
        w1f[tid] = wW1[tid];
        b2f[tid] = wb2[tid]; s2f[tid] = wg2[tid]*invs; e2f[tid] = wbe2[tid];
    }
    for (int t = tid; t < 512; t += 128) w2f[t] = wW2[t];

    int i0 = blockIdx.x * 8;
    int b = i0 >> 12;
    __syncthreads();
    for (int s = 0; s < 64; s++) {
        int e = s*128 + tid;
        int rowe = e >> 6, ce = e & 63;
        int ie = i0 + (rowe >> 4);
        int ke = rowe & 15;
        int je = g_idxS[ie*16 + ke];
        int jg = (b << 12) + je;
        grp[rowe*65 + ce] = g_cost[(size_t)jg*64 + ce] + g_costw[(size_t)jg*64 + ce];
    }
    __syncthreads();

    int nl = tid >> 4, k = tid & 15;
    int i = i0 + nl, n = i & (NN - 1);
    int j = g_idxS[i*16 + k];
    int jg = (b << 12) + j;
    float4 Pj = g_p1[jg], Pi = g_p1[i];
    float dx = Pj.x - Pi.x, dy = Pj.y - Pi.y, dz = Pj.z - Pi.z;
    float h0[8];
#pragma unroll
    for (int o = 0; o < 8; o++) {
        float z = b0f[o] + w0f[o*3]*dx + w0f[o*3+1]*dy + w0f[o*3+2]*dz;
        z = z*s0f[o] + e0f[o];
        h0[o] = fmaxf(z, 0.f);
    }
    float h1[8];
#pragma unroll
    for (int o = 0; o < 8; o++) {
        float z = b1f[o];
#pragma unroll
        for (int c = 0; c < 8; c++) z = fmaf(w1f[o*8 + c], h0[c], z);
        z = z*s1f[o] + e1f[o];
        h1[o] = fmaxf(z, 0.f);
    }
    int myrow = nl*16 + k;
    for (int c = 0; c < 64; c++) {
        float z = b2f[c];
#pragma unroll
        for (int o = 0; o < 8; o++) z = fmaf(w2f[c*8 + o], h1[o], z);
        z = fmaxf(z*s2f[c] + e2f[c], 0.f);
        float v = z * grp[myrow*65 + c];
        v += __shfl_xor_sync(0xffffffffu, v, 1);
        v += __shfl_xor_sync(0xffffffffu, v, 2);
        v += __shfl_xor_sync(0xffffffffu, v, 4);
        v += __shfl_xor_sync(0xffffffffu, v, 8);
        if (k == 0) out[((size_t)b*CMX + c)*NN + n] = v;
    }
}

// ---------------- launch ----------------
extern "C" void kernel_launch(void* const* d_in, const int* in_sizes, int n_in,
                              void* d_out, int out_size) {
    const float* xyz1    = (const float*)d_in[0];
    const float* xyz2    = (const float*)d_in[1];
    const float* xyz2w   = (const float*)d_in[2];
    const float* points1 = (const float*)d_in[3];
    const float* points2 = (const float*)d_in[4];
    const float* mlp_W0  = (const float*)d_in[5];
    const float* mlp_b0  = (const float*)d_in[6];
    const float* mlp_W1  = (const float*)d_in[7];
    const float* mlp_b1  = (const float*)d_in[8];
    const float* wn_W0   = (const float*)d_in[9];
    const float* wn_b0   = (const float*)d_in[10];
    const float* wn_g0   = (const float*)d_in[11];
    const float* wn_be0  = (const float*)d_in[12];
    const float* wn_W1   = (const float*)d_in[13];
    const float* wn_b1   = (const float*)d_in[14];
    const float* wn_g1   = (const float*)d_in[15];
    const float* wn_be1  = (const float*)d_in[16];
    const float* wn_W2   = (const float*)d_in[17];
    const float* wn_b2   = (const float*)d_in[18];
    const float* wn_g2   = (const float*)d_in[19];
    const float* wn_be2  = (const float*)d_in[20];
    float* out = (float*)d_out;

    pack_xyz_k<<<BN/256, 256>>>(xyz1, xyz2, xyz2w);
    transpose_k<<<dim3(NN/32, DD/32, 2*BB), dim3(32, 8)>>>(points1, points2);
    knn3_part1_k<<<dim3(BN/8, 4), 256>>>(mlp_W0, mlp_b0);
    mlp_k<<<2048, 128>>>(mlp_W0, mlp_W1, mlp_b1);
    wqk_k<<<dim3(NSPLIT, BB), 256>>>();
    softmax_k<<<8, 256>>>();
    cost_k<<<BN*64/256, 256>>>();
    final_k<<<BN/8, 128>>>(wn_W0, wn_b0, wn_g0, wn_be0,
                           wn_W1, wn_b1, wn_g1, wn_be1,
                           wn_W2, wn_b2, wn_g2, wn_be2, out);
}

// round 14
// speedup vs baseline: 1.2139x; 1.1263x over previous
#include <cuda_runtime.h>
#include <math_constants.h>

#define BB 2
#define NN 4096
#define DD 64
#define CMX 64
#define HH 8
#define KK 16
#define BN 8192            // BB*NN
#define NSPLIT 64          // wqk n-splits
#define FULLMASK 0xffffffffu

// ---------------- scratch (device globals; no allocation) ----------------
__device__ float4 g_p1[BN], g_p2[BN], g_p2w[BN];        // packed xyz + sqnorm
__device__ float  g_f1t[BN*DD], g_f2t[BN*DD];           // transposed features [B,N,D]
__device__ int    g_idxA[BN*KK], g_idxB[BN*KK], g_idxS[BN*KK];
__device__ float  g_part1[BN*CMX];                      // W0a·f1 + b0
__device__ float  g_pre2[BN*CMX];                       // W0b·f2[j] (no bias)
__device__ float  g_feat[BN*KK*CMX], g_featw[BN*KK*CMX];
__device__ float  g_wqkp[NSPLIT*BB*CMX*KK*KK];          // per-split partials (deterministic)
__device__ float  g_rsum[BB*CMX*KK], g_csum[BB*CMX*KK];
__device__ float  g_cost[BN*CMX], g_costw[BN*CMX];      // [b,n,c] layout

// ---------------- pack xyz -> float4(x,y,z,|p|^2) ----------------
__global__ void pack_xyz_k(const float* __restrict__ x1,
                           const float* __restrict__ x2,
                           const float* __restrict__ x2w) {
    int i = blockIdx.x * blockDim.x + threadIdx.x;
    if (i >= BN) return;
    int b = i >> 12, n = i & (NN - 1);
#pragma unroll
    for (int t = 0; t < 3; t++) {
        const float* s = (t == 0) ? x1 : (t == 1) ? x2 : x2w;
        float4* d      = (t == 0) ? g_p1 : (t == 1) ? g_p2 : g_p2w;
        float x = s[(size_t)b*3*NN + n];
        float y = s[(size_t)b*3*NN + NN + n];
        float z = s[(size_t)b*3*NN + 2*NN + n];
        d[i] = make_float4(x, y, z, x*x + y*y + z*z);
    }
}

// ---------------- transpose points [B,D,N] -> [B,N,D] ----------------
__global__ void transpose_k(const float* __restrict__ pA,
                            const float* __restrict__ pB) {
    __shared__ float t[32][33];
    int a = blockIdx.z >> 1;      // 0: points1, 1: points2
    int b = blockIdx.z & 1;
    const float* src = a ? pB : pA;
    float* dst       = a ? g_f2t : g_f1t;
    int n0 = blockIdx.x * 32, c0 = blockIdx.y * 32;
#pragma unroll
    for (int j = 0; j < 4; j++)
        t[threadIdx.y + 8*j][threadIdx.x] =
            src[((size_t)b*DD + c0 + threadIdx.y + 8*j)*NN + n0 + threadIdx.x];
    __syncthreads();
#pragma unroll
    for (int j = 0; j < 4; j++)
        dst[((size_t)b*NN + n0 + threadIdx.y + 8*j)*DD + c0 + threadIdx.x] =
            t[threadIdx.x][threadIdx.y + 8*j];
}

// ---------------- KNN body: warp-distributed top-16 in registers ----------------
__device__ __forceinline__ void knn_body(int which, int q) {
    const float4* ref = (which == 0) ? g_p2 : (which == 1) ? g_p2w : g_p1;
    int* outIdx       = (which == 0) ? g_idxA : (which == 1) ? g_idxB : g_idxS;
    int lane = threadIdx.x & 31;
    int b = q >> 12;
    const float4* refb = ref + b*NN;
    float4 Q = g_p1[q];

    float vd = CUDART_INF_F; int vi = 0x7fffffff;        // my slot of the distributed list
    float taud = CUDART_INF_F; int taui = 0x7fffffff;    // lane-15 entry (threshold)

#pragma unroll 4
    for (int j = 0; j < NN/32; j++) {
        int gi = j*32 + lane;
        float4 R = __ldg(&refb[gi]);
        float d = Q.w + R.w - 2.f*(Q.x*R.x + Q.y*R.y + Q.z*R.z);
        bool acc = (d < taud) || (d == taud && gi < taui);
        unsigned m = __ballot_sync(FULLMASK, acc);
        while (m) {
            int src = __ffs(m) - 1; m &= m - 1;
            float xd = __shfl_sync(FULLMASK, d,  src);
            int   xi = __shfl_sync(FULLMASK, gi, src);
            bool lt = (vd < xd) || (vd == xd && vi < xi);
            int pos = __popc(__ballot_sync(FULLMASK, lt) & 0xffffu);
            if (pos < 16) {
                float pd = __shfl_up_sync(FULLMASK, vd, 1);
                int   pi = __shfl_up_sync(FULLMASK, vi, 1);
                if (lane < 16) {
                    if (lane == pos)      { vd = xd; vi = xi; }
                    else if (lane > pos)  { vd = pd; vi = pi; }
                }
                taud = __shfl_sync(FULLMASK, vd, 15);
                taui = __shfl_sync(FULLMASK, vi, 15);
            }
        }
    }
    if (lane < 16) outIdx[q*KK + lane] = vi;
}

// ---------------- fused: knn x3 (y=0,1,2) + part1 (y=3) + pre2 (y=4) ----------------
__global__ __launch_bounds__(256) void knn3_part1_k(const float* __restrict__ W0,
                                                    const float* __restrict__ b0) {
    __shared__ __align__(16) float w0s[64*68];
    __shared__ __align__(16) float buf[8][64];
    int w = threadIdx.x >> 5, lane = threadIdx.x & 31;

    if (blockIdx.y < 3) {
        knn_body(blockIdx.y, blockIdx.x * 8 + w);
        return;
    }
    // plane 3: part1 = W0[:,0:64]*f1 + b0 ; plane 4: pre2 = W0[:,64:128]*f2
    int plane = blockIdx.y;
    const float* srcf = (plane == 3) ? g_f1t : g_f2t;
    float* dstp       = (plane == 3) ? g_part1 : g_pre2;
    int coff          = (plane == 3) ? 0 : 64;
    for (int t = threadIdx.x; t < 64*64; t += 256) {
        int o = t >> 6, c = t & 63;
        w0s[o*68 + c] = W0[o*131 + coff + c];
    }
    __syncthreads();
    int i = blockIdx.x*8 + w;
    buf[w][lane]      = srcf[(size_t)i*64 + lane];
    buf[w][lane + 32] = srcf[(size_t)i*64 + 32 + lane];
    __syncwarp();
    float a0 = (plane == 3) ? b0[lane]      : 0.f;
    float a1 = (plane == 3) ? b0[lane + 32] : 0.f;
#pragma unroll
    for (int c4 = 0; c4 < 16; c4++) {
        float4 wa = *(const float4*)&w0s[lane*68 + c4*4];
        float4 wb = *(const float4*)&w0s[(lane+32)*68 + c4*4];
        float4 f  = *(const float4*)&buf[w][c4*4];
        a0 = fmaf(wa.x, f.x, a0); a0 = fmaf(wa.y, f.y, a0);
        a0 = fmaf(wa.z, f.z, a0); a0 = fmaf(wa.w, f.w, a0);
        a1 = fmaf(wb.x, f.x, a1); a1 = fmaf(wb.y, f.y, a1);
        a1 = fmaf(wb.z, f.z, a1); a1 = fmaf(wb.w, f.w, a1);
    }
    dstp[(size_t)i*64 + lane]      = a0;
    dstp[(size_t)i*64 + 32 + lane] = a1;
}

// ---------------- MLP v5: warp per (a,i) group (16 rows); layer1 via part1+pre2+dir ----------------
__global__ __launch_bounds__(128) void mlp_k(const float* __restrict__ W0,
                                             const float* __restrict__ W1,
                                             const float* __restrict__ b1) {
    __shared__ __align__(16) float w1s[64*68];    // 17408B
    __shared__ float b1s[64];
    __shared__ __align__(16) float buf[4][16][68]; // 17408B
    int w = threadIdx.x >> 5, lane = threadIdx.x & 31;
    for (int t = threadIdx.x; t < 64*64; t += 128) {
        int o = t >> 6, c = t & 63;
        w1s[o*68 + c] = W1[t];
    }
    if (threadIdx.x < 64) b1s[threadIdx.x] = b1[threadIdx.x];
    __syncthreads();
    // dir weights (W0 cols 128..130) for this lane's two outputs
    float wc0x = W0[lane*131 + 128], wc0y = W0[lane*131 + 129], wc0z = W0[lane*131 + 130];
    float wc1x = W0[(lane+32)*131 + 128], wc1y = W0[(lane+32)*131 + 129], wc1z = W0[(lane+32)*131 + 130];
    float b1a = b1s[lane], b1b = b1s[lane + 32];

    const int NGRP = BN * 2;   // 16384 groups: (array, i)
    for (int g = blockIdx.x*4 + w; g < NGRP; g += gridDim.x*4) {
        int a = g >> 13;             // 0: feat, 1: featw
        int i = g & (BN - 1);
        int jgq = 0; float dx = 0.f, dy = 0.f, dz = 0.f;
        if (lane < 16) {
            int jl = (a ? g_idxB : g_idxA)[i*16 + lane];
            jgq = (i & ~(NN - 1)) + jl;
            float4 Pr = a ? g_p2w[jgq] : g_p2[jgq];
            float4 Pq = g_p1[i];
            dx = Pr.x - Pq.x; dy = Pr.y - Pq.y; dz = Pr.z - Pq.z;
        }
        float pa0 = g_part1[(size_t)i*64 + lane];
        float pa1 = g_part1[(size_t)i*64 + 32 + lane];
        float q0[16], q1[16];
#pragma unroll
        for (int r = 0; r < 16; r++) {
            int jr = __shfl_sync(FULLMASK, jgq, r);
            q0[r] = __ldg(&g_pre2[(size_t)jr*64 + lane]);
            q1[r] = __ldg(&g_pre2[(size_t)jr*64 + 32 + lane]);
        }
#pragma unroll
        for (int r = 0; r < 16; r++) {
            float dxr = __shfl_sync(FULLMASK, dx, r);
            float dyr = __shfl_sync(FULLMASK, dy, r);
            float dzr = __shfl_sync(FULLMASK, dz, r);
            float v0 = pa0 + q0[r];
            v0 = fmaf(wc0x, dxr, v0); v0 = fmaf(wc0y, dyr, v0); v0 = fmaf(wc0z, dzr, v0);
            float v1 = pa1 + q1[r];
            v1 = fmaf(wc1x, dxr, v1); v1 = fmaf(wc1y, dyr, v1); v1 = fmaf(wc1z, dzr, v1);
            v0 = v0 >= 0.f ? v0 : 0.1f*v0;
            v1 = v1 >= 0.f ? v1 : 0.1f*v1;
            buf[w][r][lane]      = v0;
            buf[w][r][lane + 32] = v1;
        }
        __syncwarp();
        float o0[16], o1[16];
#pragma unroll
        for (int r = 0; r < 16; r++) { o0[r] = b1a; o1[r] = b1b; }
#pragma unroll 2
        for (int c4 = 0; c4 < 16; c4++) {
            float4 wa = *(const float4*)&w1s[lane*68 + c4*4];
            float4 wb = *(const float4*)&w1s[(lane+32)*68 + c4*4];
#pragma unroll
            for (int r = 0; r < 16; r++) {
                float4 f = *(const float4*)&buf[w][r][c4*4];
                o0[r] = fmaf(wa.x, f.x, o0[r]); o0[r] = fmaf(wa.y, f.y, o0[r]);
                o0[r] = fmaf(wa.z, f.z, o0[r]); o0[r] = fmaf(wa.w, f.w, o0[r]);
                o1[r] = fmaf(wb.x, f.x, o1[r]); o1[r] = fmaf(wb.y, f.y, o1[r]);
                o1[r] = fmaf(wb.z, f.z, o1[r]); o1[r] = fmaf(wb.w, f.w, o1[r]);
            }
        }
        float* dst = a ? g_featw : g_feat;
        size_t r2 = (size_t)i*16;
#pragma unroll
        for (int r = 0; r < 16; r++) {
            float v0 = o0[r] >= 0.f ? o0[r] : 0.1f*o0[r];
            float v1 = o1[r] >= 0.f ? o1[r] : 0.1f*o1[r];
            dst[(r2 + r)*64 + lane]      = v0;
            dst[(r2 + r)*64 + 32 + lane] = v1;
        }
        __syncwarp();
    }
}

// ---------------- wqk v2: block = (n-split of 64, b), ALL 64 channels per block ----------------
__global__ __launch_bounds__(256) void wqk_k() {
    __shared__ float fs[16][256];       // feat  [c in subtile][n*16+k]
    __shared__ float wsm[16][256];      // featw [c in subtile][n*16+l]
    int ns = blockIdx.x;                // 0..NSPLIT-1 (64 n each)
    int b  = blockIdx.y;
    int tid = threadIdx.x;
    int nl = tid >> 4, kl = tid & 15;   // load mapping
    int kc = tid >> 4, lc = tid & 15;   // compute mapping (k,l)

    float acc[64];
#pragma unroll
    for (int c = 0; c < 64; c++) acc[c] = 0.f;

    for (int ch = 0; ch < 4; ch++) {
        int n0 = ns*64 + ch*16;
        size_t rowf = ((size_t)(b*NN + n0 + nl)*16 + kl)*64;
#pragma unroll
        for (int cp = 0; cp < 4; cp++) {
            __syncthreads();
            const float4* fp = (const float4*)(g_feat  + rowf + cp*16);
            const float4* gp = (const float4*)(g_featw + rowf + cp*16);
            int base = nl*16 + kl;
#pragma unroll
            for (int v = 0; v < 4; v++) {
                float4 u = fp[v];
                fs[v*4+0][base] = u.x; fs[v*4+1][base] = u.y;
                fs[v*4+2][base] = u.z; fs[v*4+3][base] = u.w;
                float4 t = gp[v];
                wsm[v*4+0][base] = t.x; wsm[v*4+1][base] = t.y;
                wsm[v*4+2][base] = t.z; wsm[v*4+3][base] = t.w;
            }
            __syncthreads();
#pragma unroll 2
            for (int n = 0; n < 16; n++) {
                int bk = n*16 + kc, bl = n*16 + lc;
#pragma unroll
                for (int c = 0; c < 16; c++)
                    acc[cp*16 + c] = fmaf(fs[c][bk], wsm[c][bl], acc[cp*16 + c]);
            }
        }
    }
#pragma unroll
    for (int c = 0; c < 64; c++)
        g_wqkp[(((size_t)ns*BB + b)*CMX + c)*256 + kc*16 + lc] = acc[c];
}

// ---------------- softmax + clip + row/col sums ----------------
__global__ void softmax_k() {
    int t = blockIdx.x*256 + threadIdx.x;     // <<<8,256>>> -> 2048 threads
    int k  = t & 15;
    int bc = t >> 4;                          // 0..127 = b*64+c
    if (bc >= BB*CMX) return;
    int b = bc >> 6, c = bc & 63;
    const float inv_sqrt3 = 0.57735026918962576f;
    float row[16];
#pragma unroll
    for (int l = 0; l < 16; l++) {
        float s = 0.f;
        for (int sp = 0; sp < NSPLIT; sp++)
            s += g_wqkp[(((size_t)sp*BB + b)*CMX + c)*256 + k*16 + l];
        row[l] = s;
    }
    float m = row[0];
#pragma unroll
    for (int l = 1; l < 16; l++) m = fmaxf(m, row[l]);
    float sum = 0.f;
#pragma unroll
    for (int l = 0; l < 16; l++) { row[l] = expf(row[l] - m); sum += row[l]; }
    float inv = 1.f / sum;
    float rs = 0.f;
#pragma unroll
    for (int l = 0; l < 16; l++) {
        float v = fmaxf(row[l]*inv*inv_sqrt3, 1e-10f);
        rs += v; row[l] = v;
    }
    g_rsum[bc*16 + k] = rs;
#pragma unroll
    for (int l = 0; l < 16; l++) {
        float v = row[l];
        v += __shfl_xor_sync(0xffffffffu, v, 1);
        v += __shfl_xor_sync(0xffffffffu, v, 2);
        v += __shfl_xor_sync(0xffffffffu, v, 4);
        v += __shfl_xor_sync(0xffffffffu, v, 8);
        if (k == 0) g_csum[bc*16 + l] = v;
    }
}

// ---------------- cost/costw: [b,n,c] layout for coalesced gather later ----------------
__global__ __launch_bounds__(256) void cost_k() {
    int t = blockIdx.x*256 + threadIdx.x;    // BN*64 threads
    int i = t >> 6, c = t & 63;
    int b = i >> 12;
    const float* cs = &g_csum[(size_t)(b*64 + c)*16];
    const float* rs = &g_rsum[(size_t)(b*64 + c)*16];
    float a = 0.f, aw = 0.f;
#pragma unroll
    for (int l = 0; l < 16; l++) {
        a  = fmaf(g_feat [((size_t)i*16 + l)*64 + c], cs[l], a);
        aw = fmaf(g_featw[((size_t)i*16 + l)*64 + c], rs[l], aw);
    }
    g_cost[t] = a; g_costw[t] = aw;
}

// ---------------- WeightNet + gather + final contraction ----------------
__global__ __launch_bounds__(128) void final_k(
    const float* __restrict__ wW0, const float* __restrict__ wb0,
    const float* __restrict__ wg0, const float* __restrict__ wbe0,
    const float* __restrict__ wW1, const float* __restrict__ wb1,
    const float* __restrict__ wg1, const float* __restrict__ wbe1,
    const float* __restrict__ wW2, const float* __restrict__ wb2,
    const float* __restrict__ wg2, const float* __restrict__ wbe2,
    float* __restrict__ out) {
    __shared__ float grp[128*65];           // grouped rows, padded
    __shared__ float w0f[24], b0f[8], s0f[8], e0f[8];
    __shared__ float w1f[64], b1f[8], s1f[8], e1f[8];
    __shared__ float w2f[512], b2f[64], s2f[64], e2f[64];
    int tid = threadIdx.x;
    const float invs = 1.f / sqrtf(1.f + 1e-5f);
    if (tid < 24) w0f[tid] = wW0[tid];
    if (tid < 8) {
        b0f[tid] = wb0[tid]; s0f[tid] = wg0[tid]*invs; e0f[tid] = wbe0[tid];
        b1f[tid] = wb1[tid]; s1f[tid] = wg1[tid]*invs; e1f[tid] = wbe1[tid];
    }
    if (tid < 64) {
        w1f[tid] = wW1[tid];
        b2f[tid] = wb2[tid]; s2f[tid] = wg2[tid]*invs; e2f[tid] = wbe2[tid];
    }
    for (int t = tid; t < 512; t += 128) w2f[t] = wW2[t];

    int i0 = blockIdx.x * 8;
    int b = i0 >> 12;
    __syncthreads();
    for (int s = 0; s < 64; s++) {
        int e = s*128 + tid;
        int rowe = e >> 6, ce = e & 63;
        int ie = i0 + (rowe >> 4);
        int ke = rowe & 15;
        int je = g_idxS[ie*16 + ke];
        int jg = (b << 12) + je;
        grp[rowe*65 + ce] = g_cost[(size_t)jg*64 + ce] + g_costw[(size_t)jg*64 + ce];
    }
    __syncthreads();

    int nl = tid >> 4, k = tid & 15;
    int i = i0 + nl, n = i & (NN - 1);
    int j = g_idxS[i*16 + k];
    int jg = (b << 12) + j;
    float4 Pj = g_p1[jg], Pi = g_p1[i];
    float dx = Pj.x - Pi.x, dy = Pj.y - Pi.y, dz = Pj.z - Pi.z;
    float h0[8];
#pragma unroll
    for (int o = 0; o < 8; o++) {
        float z = b0f[o] + w0f[o*3]*dx + w0f[o*3+1]*dy + w0f[o*3+2]*dz;
        z = z*s0f[o] + e0f[o];
        h0[o] = fmaxf(z, 0.f);
    }
    float h1[8];
#pragma unroll
    for (int o = 0; o < 8; o++) {
        float z = b1f[o];
#pragma unroll
        for (int c = 0; c < 8; c++) z = fmaf(w1f[o*8 + c], h0[c], z);
        z = z*s1f[o] + e1f[o];
        h1[o] = fmaxf(z, 0.f);
    }
    int myrow = nl*16 + k;
    for (int c = 0; c < 64; c++) {
        float z = b2f[c];
#pragma unroll
        for (int o = 0; o < 8; o++) z = fmaf(w2f[c*8 + o], h1[o], z);
        z = fmaxf(z*s2f[c] + e2f[c], 0.f);
        float v = z * grp[myrow*65 + c];
        v += __shfl_xor_sync(0xffffffffu, v, 1);
        v += __shfl_xor_sync(0xffffffffu, v, 2);
        v += __shfl_xor_sync(0xffffffffu, v, 4);
        v += __shfl_xor_sync(0xffffffffu, v, 8);
        if (k == 0) out[((size_t)b*CMX + c)*NN + n] = v;
    }
}

// ---------------- launch ----------------
extern "C" void kernel_launch(void* const* d_in, const int* in_sizes, int n_in,
                              void* d_out, int out_size) {
    const float* xyz1    = (const float*)d_in[0];
    const float* xyz2    = (const float*)d_in[1];
    const float* xyz2w   = (const float*)d_in[2];
    const float* points1 = (const float*)d_in[3];
    const float* points2 = (const float*)d_in[4];
    const float* mlp_W0  = (const float*)d_in[5];
    const float* mlp_b0  = (const float*)d_in[6];
    const float* mlp_W1  = (const float*)d_in[7];
    const float* mlp_b1  = (const float*)d_in[8];
    const float* wn_W0   = (const float*)d_in[9];
    const float* wn_b0   = (const float*)d_in[10];
    const float* wn_g0   = (const float*)d_in[11];
    const float* wn_be0  = (const float*)d_in[12];
    const float* wn_W1   = (const float*)d_in[13];
    const float* wn_b1   = (const float*)d_in[14];
    const float* wn_g1   = (const float*)d_in[15];
    const float* wn_be1  = (const float*)d_in[16];
    const float* wn_W2   = (const float*)d_in[17];
    const float* wn_b2   = (const float*)d_in[18];
    const float* wn_g2   = (const float*)d_in[19];
    const float* wn_be2  = (const float*)d_in[20];
    float* out = (float*)d_out;

    pack_xyz_k<<<BN/256, 256>>>(xyz1, xyz2, xyz2w);
    transpose_k<<<dim3(NN/32, DD/32, 2*BB), dim3(32, 8)>>>(points1, points2);
    knn3_part1_k<<<dim3(BN/8, 5), 256>>>(mlp_W0, mlp_b0);
    mlp_k<<<2048, 128>>>(mlp_W0, mlp_W1, mlp_b1);
    wqk_k<<<dim3(NSPLIT, BB), 256>>>();
    softmax_k<<<8, 256>>>();
    cost_k<<<BN*64/256, 256>>>();
    final_k<<<BN/8, 128>>>(wn_W0, wn_b0, wn_g0, wn_be0,
                           wn_W1, wn_b1, wn_g1, wn_be1,
                           wn_W2, wn_b2, wn_g2, wn_be2, out);
}

// round 15
// speedup vs baseline: 1.2357x; 1.0179x over previous
#include <cuda_runtime.h>
#include <math_constants.h>

#define BB 2
#define NN 4096
#define DD 64
#define CMX 64
#define HH 8
#define KK 16
#define BN 8192            // BB*NN
#define NSPLIT 64          // wqk n-splits
#define FULLMASK 0xffffffffu

// ---------------- scratch (device globals; no allocation) ----------------
__device__ float4 g_p1[BN], g_p2[BN], g_p2w[BN];        // packed xyz + sqnorm
__device__ float  g_f1t[BN*DD], g_f2t[BN*DD];           // transposed features [B,N,D]
__device__ int    g_idxA[BN*KK], g_idxB[BN*KK], g_idxS[BN*KK];
__device__ float  g_part1[BN*CMX];                      // W0a·f1 + b0
__device__ float  g_pre2[BN*CMX];                       // W0b·f2[j] (no bias)
__device__ float  g_feat[BN*KK*CMX], g_featw[BN*KK*CMX];
__device__ float  g_wqkp[NSPLIT*BB*CMX*KK*KK];          // per-split partials (deterministic)
__device__ float  g_rsum[BB*CMX*KK], g_csum[BB*CMX*KK];
__device__ float  g_cost[BN*CMX], g_costw[BN*CMX];      // [b,n,c] layout

// ---------------- pack xyz -> float4(x,y,z,|p|^2) ----------------
__global__ void pack_xyz_k(const float* __restrict__ x1,
                           const float* __restrict__ x2,
                           const float* __restrict__ x2w) {
    int i = blockIdx.x * blockDim.x + threadIdx.x;
    if (i >= BN) return;
    int b = i >> 12, n = i & (NN - 1);
#pragma unroll
    for (int t = 0; t < 3; t++) {
        const float* s = (t == 0) ? x1 : (t == 1) ? x2 : x2w;
        float4* d      = (t == 0) ? g_p1 : (t == 1) ? g_p2 : g_p2w;
        float x = s[(size_t)b*3*NN + n];
        float y = s[(size_t)b*3*NN + NN + n];
        float z = s[(size_t)b*3*NN + 2*NN + n];
        d[i] = make_float4(x, y, z, x*x + y*y + z*z);
    }
}

// ---------------- transpose points [B,D,N] -> [B,N,D] ----------------
__global__ void transpose_k(const float* __restrict__ pA,
                            const float* __restrict__ pB) {
    __shared__ float t[32][33];
    int a = blockIdx.z >> 1;      // 0: points1, 1: points2
    int b = blockIdx.z & 1;
    const float* src = a ? pB : pA;
    float* dst       = a ? g_f2t : g_f1t;
    int n0 = blockIdx.x * 32, c0 = blockIdx.y * 32;
#pragma unroll
    for (int j = 0; j < 4; j++)
        t[threadIdx.y + 8*j][threadIdx.x] =
            src[((size_t)b*DD + c0 + threadIdx.y + 8*j)*NN + n0 + threadIdx.x];
    __syncthreads();
#pragma unroll
    for (int j = 0; j < 4; j++)
        dst[((size_t)b*NN + n0 + threadIdx.y + 8*j)*DD + c0 + threadIdx.x] =
            t[threadIdx.x][threadIdx.y + 8*j];
}

// ---------------- KNN body: warp-distributed top-16 in registers, tau-pruned ----------------
__device__ __forceinline__ void knn_body(int which, int q) {
    const float4* ref = (which == 0) ? g_p2 : (which == 1) ? g_p2w : g_p1;
    int* outIdx       = (which == 0) ? g_idxA : (which == 1) ? g_idxB : g_idxS;
    int lane = threadIdx.x & 31;
    int b = q >> 12;
    const float4* refb = ref + b*NN;
    float4 Q = g_p1[q];

    float vd = CUDART_INF_F; int vi = 0x7fffffff;        // my slot of the distributed list
    float taud = CUDART_INF_F; int taui = 0x7fffffff;    // lane-15 entry (threshold)

#pragma unroll 4
    for (int j = 0; j < NN/32; j++) {
        int gi = j*32 + lane;
        float4 R = __ldg(&refb[gi]);
        float d = Q.w + R.w - 2.f*(Q.x*R.x + Q.y*R.y + Q.z*R.z);
        bool acc = (d < taud) || (d == taud && gi < taui);
        unsigned m = __ballot_sync(FULLMASK, acc);
        while (m) {
            int src = __ffs(m) - 1; m &= m - 1;
            float xd = __shfl_sync(FULLMASK, d,  src);
            int   xi = __shfl_sync(FULLMASK, gi, src);
            // re-check against updated tau (warp-uniform); pruned inserts are no-ops
            if (xd > taud || (xd == taud && xi > taui)) continue;
            bool lt = (vd < xd) || (vd == xd && vi < xi);
            int pos = __popc(__ballot_sync(FULLMASK, lt) & 0xffffu);
            if (pos < 16) {
                float pd = __shfl_up_sync(FULLMASK, vd, 1);
                int   pi = __shfl_up_sync(FULLMASK, vi, 1);
                if (lane < 16) {
                    if (lane == pos)      { vd = xd; vi = xi; }
                    else if (lane > pos)  { vd = pd; vi = pi; }
                }
                taud = __shfl_sync(FULLMASK, vd, 15);
                taui = __shfl_sync(FULLMASK, vi, 15);
            }
        }
    }
    if (lane < 16) outIdx[q*KK + lane] = vi;
}

// ---------------- fused: knn x3 (y=0,1,2) + part1 (y=3) + pre2 (y=4) ----------------
__global__ __launch_bounds__(256) void knn3_part1_k(const float* __restrict__ W0,
                                                    const float* __restrict__ b0) {
    __shared__ __align__(16) float w0s[64*68];
    __shared__ __align__(16) float buf[8][64];
    int w = threadIdx.x >> 5, lane = threadIdx.x & 31;

    if (blockIdx.y < 3) {
        knn_body(blockIdx.y, blockIdx.x * 8 + w);
        return;
    }
    // plane 3: part1 = W0[:,0:64]*f1 + b0 ; plane 4: pre2 = W0[:,64:128]*f2
    int plane = blockIdx.y;
    const float* srcf = (plane == 3) ? g_f1t : g_f2t;
    float* dstp       = (plane == 3) ? g_part1 : g_pre2;
    int coff          = (plane == 3) ? 0 : 64;
    for (int t = threadIdx.x; t < 64*64; t += 256) {
        int o = t >> 6, c = t & 63;
        w0s[o*68 + c] = W0[o*131 + coff + c];
    }
    __syncthreads();
    int i = blockIdx.x*8 + w;
    buf[w][lane]      = srcf[(size_t)i*64 + lane];
    buf[w][lane + 32] = srcf[(size_t)i*64 + 32 + lane];
    __syncwarp();
    float a0 = (plane == 3) ? b0[lane]      : 0.f;
    float a1 = (plane == 3) ? b0[lane + 32] : 0.f;
#pragma unroll
    for (int c4 = 0; c4 < 16; c4++) {
        float4 wa = *(const float4*)&w0s[lane*68 + c4*4];
        float4 wb = *(const float4*)&w0s[(lane+32)*68 + c4*4];
        float4 f  = *(const float4*)&buf[w][c4*4];
        a0 = fmaf(wa.x, f.x, a0); a0 = fmaf(wa.y, f.y, a0);
        a0 = fmaf(wa.z, f.z, a0); a0 = fmaf(wa.w, f.w, a0);
        a1 = fmaf(wb.x, f.x, a1); a1 = fmaf(wb.y, f.y, a1);
        a1 = fmaf(wb.z, f.z, a1); a1 = fmaf(wb.w, f.w, a1);
    }
    dstp[(size_t)i*64 + lane]      = a0;
    dstp[(size_t)i*64 + 32 + lane] = a1;
}

// ---------------- MLP v5: warp per (a,i) group (16 rows); layer1 via part1+pre2+dir ----------------
__global__ __launch_bounds__(128) void mlp_k(const float* __restrict__ W0,
                                             const float* __restrict__ W1,
                                             const float* __restrict__ b1) {
    __shared__ __align__(16) float w1s[64*68];    // 17408B
    __shared__ float b1s[64];
    __shared__ __align__(16) float buf[4][16][68]; // 17408B
    int w = threadIdx.x >> 5, lane = threadIdx.x & 31;
    for (int t = threadIdx.x; t < 64*64; t += 128) {
        int o = t >> 6, c = t & 63;
        w1s[o*68 + c] = W1[t];
    }
    if (threadIdx.x < 64) b1s[threadIdx.x] = b1[threadIdx.x];
    __syncthreads();
    // dir weights (W0 cols 128..130) for this lane's two outputs
    float wc0x = W0[lane*131 + 128], wc0y = W0[lane*131 + 129], wc0z = W0[lane*131 + 130];
    float wc1x = W0[(lane+32)*131 + 128], wc1y = W0[(lane+32)*131 + 129], wc1z = W0[(lane+32)*131 + 130];
    float b1a = b1s[lane], b1b = b1s[lane + 32];

    const int NGRP = BN * 2;   // 16384 groups: (array, i)
    for (int g = blockIdx.x*4 + w; g < NGRP; g += gridDim.x*4) {
        int a = g >> 13;             // 0: feat, 1: featw
        int i = g & (BN - 1);
        int jgq = 0; float dx = 0.f, dy = 0.f, dz = 0.f;
        if (lane < 16) {
            int jl = (a ? g_idxB : g_idxA)[i*16 + lane];
            jgq = (i & ~(NN - 1)) + jl;
            float4 Pr = a ? g_p2w[jgq] : g_p2[jgq];
            float4 Pq = g_p1[i];
            dx = Pr.x - Pq.x; dy = Pr.y - Pq.y; dz = Pr.z - Pq.z;
        }
        float pa0 = g_part1[(size_t)i*64 + lane];
        float pa1 = g_part1[(size_t)i*64 + 32 + lane];
        float q0[16], q1[16];
#pragma unroll
        for (int r = 0; r < 16; r++) {
            int jr = __shfl_sync(FULLMASK, jgq, r);
            q0[r] = __ldg(&g_pre2[(size_t)jr*64 + lane]);
            q1[r] = __ldg(&g_pre2[(size_t)jr*64 + 32 + lane]);
        }
#pragma unroll
        for (int r = 0; r < 16; r++) {
            float dxr = __shfl_sync(FULLMASK, dx, r);
            float dyr = __shfl_sync(FULLMASK, dy, r);
            float dzr = __shfl_sync(FULLMASK, dz, r);
            float v0 = pa0 + q0[r];
            v0 = fmaf(wc0x, dxr, v0); v0 = fmaf(wc0y, dyr, v0); v0 = fmaf(wc0z, dzr, v0);
            float v1 = pa1 + q1[r];
            v1 = fmaf(wc1x, dxr, v1); v1 = fmaf(wc1y, dyr, v1); v1 = fmaf(wc1z, dzr, v1);
            v0 = v0 >= 0.f ? v0 : 0.1f*v0;
            v1 = v1 >= 0.f ? v1 : 0.1f*v1;
            buf[w][r][lane]      = v0;
            buf[w][r][lane + 32] = v1;
        }
        __syncwarp();
        float o0[16], o1[16];
#pragma unroll
        for (int r = 0; r < 16; r++) { o0[r] = b1a; o1[r] = b1b; }
#pragma unroll 2
        for (int c4 = 0; c4 < 16; c4++) {
            float4 wa = *(const float4*)&w1s[lane*68 + c4*4];
            float4 wb = *(const float4*)&w1s[(lane+32)*68 + c4*4];
#pragma unroll
            for (int r = 0; r < 16; r++) {
                float4 f = *(const float4*)&buf[w][r][c4*4];
                o0[r] = fmaf(wa.x, f.x, o0[r]); o0[r] = fmaf(wa.y, f.y, o0[r]);
                o0[r] = fmaf(wa.z, f.z, o0[r]); o0[r] = fmaf(wa.w, f.w, o0[r]);
                o1[r] = fmaf(wb.x, f.x, o1[r]); o1[r] = fmaf(wb.y, f.y, o1[r]);
                o1[r] = fmaf(wb.z, f.z, o1[r]); o1[r] = fmaf(wb.w, f.w, o1[r]);
            }
        }
        float* dst = a ? g_featw : g_feat;
        size_t r2 = (size_t)i*16;
#pragma unroll
        for (int r = 0; r < 16; r++) {
            float v0 = o0[r] >= 0.f ? o0[r] : 0.1f*o0[r];
            float v1 = o1[r] >= 0.f ? o1[r] : 0.1f*o1[r];
            dst[(r2 + r)*64 + lane]      = v0;
            dst[(r2 + r)*64 + 32 + lane] = v1;
        }
        __syncwarp();
    }
}

// ---------------- wqk v3: register-blocked; thread = (c, k-quad), acc[4][16] ----------------
__global__ __launch_bounds__(256) void wqk_k() {
    __shared__ __align__(16) float sf[64][68];   // 4n x 16k rows of feat,  64 c each
    __shared__ __align__(16) float sw[64][68];   // 4n x 16l rows of featw
    int ns = blockIdx.x;                // 0..NSPLIT-1 (64 n each)
    int b  = blockIdx.y;
    int tid = threadIdx.x;
    int c  = tid & 63;                  // channel
    int kq = tid >> 6;                  // k-quad 0..3

    float acc[4][16];
#pragma unroll
    for (int r = 0; r < 4; r++)
#pragma unroll
        for (int l = 0; l < 16; l++) acc[r][l] = 0.f;

    for (int ch = 0; ch < 16; ch++) {            // chunks of 4 n
        int n0 = ns*64 + ch*4;
        size_t rowbase = ((size_t)(b*NN + n0))*16;   // first (n,k) row
        __syncthreads();
#pragma unroll
        for (int v = 0; v < 4; v++) {
            int idx = v*256 + tid;               // 0..1023
            int row = idx >> 4, cf = (idx & 15)*4;
            *(float4*)&sf[row][cf] = *(const float4*)&g_feat [(rowbase + row)*64 + cf];
            *(float4*)&sw[row][cf] = *(const float4*)&g_featw[(rowbase + row)*64 + cf];
        }
        __syncthreads();
#pragma unroll
        for (int n = 0; n < 4; n++) {
            float wreg[16];
#pragma unroll
            for (int l = 0; l < 16; l++) wreg[l] = sw[n*16 + l][c];
            float fr[4];
#pragma unroll
            for (int r = 0; r < 4; r++) fr[r] = sf[n*16 + kq*4 + r][c];
#pragma unroll
            for (int r = 0; r < 4; r++)
#pragma unroll
                for (int l = 0; l < 16; l++)
                    acc[r][l] = fmaf(fr[r], wreg[l], acc[r][l]);
        }
    }
    size_t obase = (((size_t)ns*BB + b)*CMX + c)*256;
#pragma unroll
    for (int r = 0; r < 4; r++)
#pragma unroll
        for (int l = 0; l < 16; l++)
            g_wqkp[obase + (kq*4 + r)*16 + l] = acc[r][l];
}

// ---------------- softmax + clip + row/col sums ----------------
__global__ void softmax_k() {
    int t = blockIdx.x*256 + threadIdx.x;     // <<<8,256>>> -> 2048 threads
    int k  = t & 15;
    int bc = t >> 4;                          // 0..127 = b*64+c
    if (bc >= BB*CMX) return;
    int b = bc >> 6, c = bc & 63;
    const float inv_sqrt3 = 0.57735026918962576f;
    float row[16];
#pragma unroll
    for (int l = 0; l < 16; l++) {
        float s = 0.f;
        for (int sp = 0; sp < NSPLIT; sp++)
            s += g_wqkp[(((size_t)sp*BB + b)*CMX + c)*256 + k*16 + l];
        row[l] = s;
    }
    float m = row[0];
#pragma unroll
    for (int l = 1; l < 16; l++) m = fmaxf(m, row[l]);
    float sum = 0.f;
#pragma unroll
    for (int l = 0; l < 16; l++) { row[l] = expf(row[l] - m); sum += row[l]; }
    float inv = 1.f / sum;
    float rs = 0.f;
#pragma unroll
    for (int l = 0; l < 16; l++) {
        float v = fmaxf(row[l]*inv*inv_sqrt3, 1e-10f);
        rs += v; row[l] = v;
    }
    g_rsum[bc*16 + k] = rs;
#pragma unroll
    for (int l = 0; l < 16; l++) {
        float v = row[l];
        v += __shfl_xor_sync(0xffffffffu, v, 1);
        v += __shfl_xor_sync(0xffffffffu, v, 2);
        v += __shfl_xor_sync(0xffffffffu, v, 4);
        v += __shfl_xor_sync(0xffffffffu, v, 8);
        if (k == 0) g_csum[bc*16 + l] = v;
    }
}

// ---------------- cost/costw: [b,n,c] layout for coalesced gather later ----------------
__global__ __launch_bounds__(256) void cost_k() {
    int t = blockIdx.x*256 + threadIdx.x;    // BN*64 threads
    int i = t >> 6, c = t & 63;
    int b = i >> 12;
    const float* cs = &g_csum[(size_t)(b*64 + c)*16];
    const float* rs = &g_rsum[(size_t)(b*64 + c)*16];
    float a = 0.f, aw = 0.f;
#pragma unroll
    for (int l = 0; l < 16; l++) {
        a  = fmaf(g_feat [((size_t)i*16 + l)*64 + c], cs[l], a);
        aw = fmaf(g_featw[((size_t)i*16 + l)*64 + c], rs[l], aw);
    }
    g_cost[t] = a; g_costw[t] = aw;
}

// ---------------- WeightNet + gather + final contraction ----------------
__global__ __launch_bounds__(128) void final_k(
    const float* __restrict__ wW0, const float* __restrict__ wb0,
    const float* __restrict__ wg0, const float* __restrict__ wbe0,
    const float* __restrict__ wW1, const float* __restrict__ wb1,
    const float* __restrict__ wg1, const float* __restrict__ wbe1,
    const float* __restrict__ wW2, const float* __restrict__ wb2,
    const float* __restrict__ wg2, const float* __restrict__ wbe2,
    float* __restrict__ out) {
    __shared__ float grp[128*65];           // grouped rows, padded
    __shared__ float w0f[24], b0f[8], s0f[8], e0f[8];
    __shared__ float w1f[64], b1f[8], s1f[8], e1f[8];
    __shared__ float w2f[512], b2f[64], s2f[64], e2f[64];
    int tid = threadIdx.x;
    const float invs = 1.f / sqrtf(1.f + 1e-5f);
    if (tid < 24) w0f[tid] = wW0[tid];
    if (tid < 8) {
        b0f[tid] = wb0[tid]; s0f[tid] = wg0[tid]*invs; e0f[tid] = wbe0[tid];
        b1f[tid] = wb1[tid]; s1f[tid] = wg1[tid]*invs; e1f[tid] = wbe1[tid];
    }
    if (tid < 64) {
        w1f[tid] = wW1[tid];
        b2f[tid] = wb2[tid]; s2f[tid] = wg2[tid]*invs; e2f[tid] = wbe2[tid];
    }
    for (int t = tid; t < 512; t += 128) w2f[t] = wW2[t];

    int i0 = blockIdx.x * 8;
    int b = i0 >> 12;
    __syncthreads();
    for (int s = 0; s < 64; s++) {
        int e = s*128 + tid;
        int rowe = e >> 6, ce = e & 63;
        int ie = i0 + (rowe >> 4);
        int ke = rowe & 15;
        int je = g_idxS[ie*16 + ke];
        int jg = (b << 12) + je;
        grp[rowe*65 + ce] = g_cost[(size_t)jg*64 + ce] + g_costw[(size_t)jg*64 + ce];
    }
    __syncthreads();

    int nl = tid >> 4, k = tid & 15;
    int i = i0 + nl, n = i & (NN - 1);
    int j = g_idxS[i*16 + k];
    int jg = (b << 12) + j;
    float4 Pj = g_p1[jg], Pi = g_p1[i];
    float dx = Pj.x - Pi.x, dy = Pj.y - Pi.y, dz = Pj.z - Pi.z;
    float h0[8];
#pragma unroll
    for (int o = 0; o < 8; o++) {
        float z = b0f[o] + w0f[o*3]*dx + w0f[o*3+1]*dy + w0f[o*3+2]*dz;
        z = z*s0f[o] + e0f[o];
        h0[o] = fmaxf(z, 0.f);
    }
    float h1[8];
#pragma unroll
    for (int o = 0; o < 8; o++) {
        float z = b1f[o];
#pragma unroll
        for (int c = 0; c < 8; c++) z = fmaf(w1f[o*8 + c], h0[c], z);
        z = z*s1f[o] + e1f[o];
        h1[o] = fmaxf(z, 0.f);
    }
    int myrow = nl*16 + k;
    for (int c = 0; c < 64; c++) {
        float z = b2f[c];
#pragma unroll
        for (int o = 0; o < 8; o++) z = fmaf(w2f[c*8 + o], h1[o], z);
        z = fmaxf(z*s2f[c] + e2f[c], 0.f);
        float v = z * grp[myrow*65 + c];
        v += __shfl_xor_sync(0xffffffffu, v, 1);
        v += __shfl_xor_sync(0xffffffffu, v, 2);
        v += __shfl_xor_sync(0xffffffffu, v, 4);
        v += __shfl_xor_sync(0xffffffffu, v, 8);
        if (k == 0) out[((size_t)b*CMX + c)*NN + n] = v;
    }
}

// ---------------- launch ----------------
extern "C" void kernel_launch(void* const* d_in, const int* in_sizes, int n_in,
                              void* d_out, int out_size) {
    const float* xyz1    = (const float*)d_in[0];
    const float* xyz2    = (const float*)d_in[1];
    const float* xyz2w   = (const float*)d_in[2];
    const float* points1 = (const float*)d_in[3];
    const float* points2 = (const float*)d_in[4];
    const float* mlp_W0  = (const float*)d_in[5];
    const float* mlp_b0  = (const float*)d_in[6];
    const float* mlp_W1  = (const float*)d_in[7];
    const float* mlp_b1  = (const float*)d_in[8];
    const float* wn_W0   = (const float*)d_in[9];
    const float* wn_b0   = (const float*)d_in[10];
    const float* wn_g0   = (const float*)d_in[11];
    const float* wn_be0  = (const float*)d_in[12];
    const float* wn_W1   = (const float*)d_in[13];
    const float* wn_b1   = (const float*)d_in[14];
    const float* wn_g1   = (const float*)d_in[15];
    const float* wn_be1  = (const float*)d_in[16];
    const float* wn_W2   = (const float*)d_in[17];
    const float* wn_b2   = (const float*)d_in[18];
    const float* wn_g2   = (const float*)d_in[19];
    const float* wn_be2  = (const float*)d_in[20];
    float* out = (float*)d_out;

    pack_xyz_k<<<BN/256, 256>>>(xyz1, xyz2, xyz2w);
    transpose_k<<<dim3(NN/32, DD/32, 2*BB), dim3(32, 8)>>>(points1, points2);
    knn3_part1_k<<<dim3(BN/8, 5), 256>>>(mlp_W0, mlp_b0);
    mlp_k<<<2048, 128>>>(mlp_W0, mlp_W1, mlp_b1);
    wqk_k<<<dim3(NSPLIT, BB), 256>>>();
    softmax_k<<<8, 256>>>();
    cost_k<<<BN*64/256, 256>>>();
    final_k<<<BN/8, 128>>>(wn_W0, wn_b0, wn_g0, wn_be0,
                           wn_W1, wn_b1, wn_g1, wn_be1,
                           wn_W2, wn_b2, wn_g2, wn_be2, out);
}

// round 16
// speedup vs baseline: 1.2701x; 1.0279x over previous
#include <cuda_runtime.h>
#include <math_constants.h>

#define BB 2
#define NN 4096
#define DD 64
#define CMX 64
#define HH 8
#define KK 16
#define BN 8192            // BB*NN
#define NSPLIT 64          // wqk n-splits
#define FULLMASK 0xffffffffu

// ---------------- scratch (device globals; no allocation) ----------------
__device__ float4 g_p1[BN], g_p2[BN], g_p2w[BN];        // packed xyz + sqnorm
__device__ float  g_f1t[BN*DD], g_f2t[BN*DD];           // transposed features [B,N,D]
__device__ int    g_idxA[BN*KK], g_idxB[BN*KK], g_idxS[BN*KK];
__device__ float  g_part1[BN*CMX];                      // W0a·f1 + b0
__device__ float  g_pre2[BN*CMX];                       // W0b·f2[j] (no bias)
__device__ float  g_feat[BN*KK*CMX], g_featw[BN*KK*CMX];
__device__ float  g_wqkp[NSPLIT*BB*KK*KK*CMX];          // [sp][b][k*16+l][c] (coalesced c)
__device__ float  g_rsum[BB*CMX*KK], g_csum[BB*CMX*KK];
__device__ float  g_cost[BN*CMX], g_costw[BN*CMX];      // [b,n,c] layout

// ---------------- prep: transpose planes (z=0..3) + pack xyz (z=4) ----------------
__global__ void prep_k(const float* __restrict__ pA,
                       const float* __restrict__ pB,
                       const float* __restrict__ x1,
                       const float* __restrict__ x2,
                       const float* __restrict__ x2w) {
    __shared__ float t[32][33];
    int z = blockIdx.z;
    if (z < 4) {
        int a = z >> 1;      // 0: points1, 1: points2
        int b = z & 1;
        const float* src = a ? pB : pA;
        float* dst       = a ? g_f2t : g_f1t;
        int n0 = blockIdx.x * 32, c0 = blockIdx.y * 32;
#pragma unroll
        for (int j = 0; j < 4; j++)
            t[threadIdx.y + 8*j][threadIdx.x] =
                src[((size_t)b*DD + c0 + threadIdx.y + 8*j)*NN + n0 + threadIdx.x];
        __syncthreads();
#pragma unroll
        for (int j = 0; j < 4; j++)
            dst[((size_t)b*NN + n0 + threadIdx.y + 8*j)*DD + c0 + threadIdx.x] =
                t[threadIdx.x][threadIdx.y + 8*j];
        return;
    }
    // pack plane: first 32 flat blocks cover BN points
    int fb = blockIdx.y*128 + blockIdx.x;
    if (fb >= 32) return;
    int tid = threadIdx.y*32 + threadIdx.x;
    int i = fb*256 + tid;
    int b = i >> 12, n = i & (NN - 1);
#pragma unroll
    for (int tt = 0; tt < 3; tt++) {
        const float* s = (tt == 0) ? x1 : (tt == 1) ? x2 : x2w;
        float4* d      = (tt == 0) ? g_p1 : (tt == 1) ? g_p2 : g_p2w;
        float x = s[(size_t)b*3*NN + n];
        float y = s[(size_t)b*3*NN + NN + n];
        float z3 = s[(size_t)b*3*NN + 2*NN + n];
        d[i] = make_float4(x, y, z3, x*x + y*y + z3*z3);
    }
}

// ---------------- KNN body: warp-distributed top-16 in registers, tau-pruned ----------------
__device__ __forceinline__ void knn_body(int which, int q) {
    const float4* ref = (which == 0) ? g_p2 : (which == 1) ? g_p2w : g_p1;
    int* outIdx       = (which == 0) ? g_idxA : (which == 1) ? g_idxB : g_idxS;
    int lane = threadIdx.x & 31;
    int b = q >> 12;
    const float4* refb = ref + b*NN;
    float4 Q = g_p1[q];

    float vd = CUDART_INF_F; int vi = 0x7fffffff;        // my slot of the distributed list
    float taud = CUDART_INF_F; int taui = 0x7fffffff;    // lane-15 entry (threshold)

#pragma unroll 4
    for (int j = 0; j < NN/32; j++) {
        int gi = j*32 + lane;
        float4 R = __ldg(&refb[gi]);
        float d = Q.w + R.w - 2.f*(Q.x*R.x + Q.y*R.y + Q.z*R.z);
        bool acc = (d < taud) || (d == taud && gi < taui);
        unsigned m = __ballot_sync(FULLMASK, acc);
        while (m) {
            int src = __ffs(m) - 1; m &= m - 1;
            float xd = __shfl_sync(FULLMASK, d,  src);
            int   xi = __shfl_sync(FULLMASK, gi, src);
            if (xd > taud || (xd == taud && xi > taui)) continue;
            bool lt = (vd < xd) || (vd == xd && vi < xi);
            int pos = __popc(__ballot_sync(FULLMASK, lt) & 0xffffu);
            if (pos < 16) {
                float pd = __shfl_up_sync(FULLMASK, vd, 1);
                int   pi = __shfl_up_sync(FULLMASK, vi, 1);
                if (lane < 16) {
                    if (lane == pos)      { vd = xd; vi = xi; }
                    else if (lane > pos)  { vd = pd; vi = pi; }
                }
                taud = __shfl_sync(FULLMASK, vd, 15);
                taui = __shfl_sync(FULLMASK, vi, 15);
            }
        }
    }
    if (lane < 16) outIdx[q*KK + lane] = vi;
}

// ---------------- fused: knn x3 (y=0,1,2) + part1 (y=3) + pre2 (y=4) ----------------
__global__ __launch_bounds__(256) void knn3_part1_k(const float* __restrict__ W0,
                                                    const float* __restrict__ b0) {
    __shared__ __align__(16) float w0s[64*68];
    __shared__ __align__(16) float buf[8][64];
    int w = threadIdx.x >> 5, lane = threadIdx.x & 31;

    if (blockIdx.y < 3) {
        knn_body(blockIdx.y, blockIdx.x * 8 + w);
        return;
    }
    int plane = blockIdx.y;
    const float* srcf = (plane == 3) ? g_f1t : g_f2t;
    float* dstp       = (plane == 3) ? g_part1 : g_pre2;
    int coff          = (plane == 3) ? 0 : 64;
    for (int t = threadIdx.x; t < 64*64; t += 256) {
        int o = t >> 6, c = t & 63;
        w0s[o*68 + c] = W0[o*131 + coff + c];
    }
    __syncthreads();
    int i = blockIdx.x*8 + w;
    buf[w][lane]      = srcf[(size_t)i*64 + lane];
    buf[w][lane + 32] = srcf[(size_t)i*64 + 32 + lane];
    __syncwarp();
    float a0 = (plane == 3) ? b0[lane]      : 0.f;
    float a1 = (plane == 3) ? b0[lane + 32] : 0.f;
#pragma unroll
    for (int c4 = 0; c4 < 16; c4++) {
        float4 wa = *(const float4*)&w0s[lane*68 + c4*4];
        float4 wb = *(const float4*)&w0s[(lane+32)*68 + c4*4];
        float4 f  = *(const float4*)&buf[w][c4*4];
        a0 = fmaf(wa.x, f.x, a0); a0 = fmaf(wa.y, f.y, a0);
        a0 = fmaf(wa.z, f.z, a0); a0 = fmaf(wa.w, f.w, a0);
        a1 = fmaf(wb.x, f.x, a1); a1 = fmaf(wb.y, f.y, a1);
        a1 = fmaf(wb.z, f.z, a1); a1 = fmaf(wb.w, f.w, a1);
    }
    dstp[(size_t)i*64 + lane]      = a0;
    dstp[(size_t)i*64 + 32 + lane] = a1;
}

// ---------------- MLP v5: warp per (a,i) group (16 rows); layer1 via part1+pre2+dir ----------------
__global__ __launch_bounds__(128) void mlp_k(const float* __restrict__ W0,
                                             const float* __restrict__ W1,
                                             const float* __restrict__ b1) {
    __shared__ __align__(16) float w1s[64*68];    // 17408B
    __shared__ float b1s[64];
    __shared__ __align__(16) float buf[4][16][68]; // 17408B
    int w = threadIdx.x >> 5, lane = threadIdx.x & 31;
    for (int t = threadIdx.x; t < 64*64; t += 128) {
        int o = t >> 6, c = t & 63;
        w1s[o*68 + c] = W1[t];
    }
    if (threadIdx.x < 64) b1s[threadIdx.x] = b1[threadIdx.x];
    __syncthreads();
    float wc0x = W0[lane*131 + 128], wc0y = W0[lane*131 + 129], wc0z = W0[lane*131 + 130];
    float wc1x = W0[(lane+32)*131 + 128], wc1y = W0[(lane+32)*131 + 129], wc1z = W0[(lane+32)*131 + 130];
    float b1a = b1s[lane], b1b = b1s[lane + 32];

    const int NGRP = BN * 2;   // 16384 groups: (array, i)
    for (int g = blockIdx.x*4 + w; g < NGRP; g += gridDim.x*4) {
        int a = g >> 13;             // 0: feat, 1: featw
        int i = g & (BN - 1);
        int jgq = 0; float dx = 0.f, dy = 0.f, dz = 0.f;
        if (lane < 16) {
            int jl = (a ? g_idxB : g_idxA)[i*16 + lane];
            jgq = (i & ~(NN - 1)) + jl;
            float4 Pr = a ? g_p2w[jgq] : g_p2[jgq];
            float4 Pq = g_p1[i];
            dx = Pr.x - Pq.x; dy = Pr.y - Pq.y; dz = Pr.z - Pq.z;
        }
        float pa0 = g_part1[(size_t)i*64 + lane];
        float pa1 = g_part1[(size_t)i*64 + 32 + lane];
        float q0[16], q1[16];
#pragma unroll
        for (int r = 0; r < 16; r++) {
            int jr = __shfl_sync(FULLMASK, jgq, r);
            q0[r] = __ldg(&g_pre2[(size_t)jr*64 + lane]);
            q1[r] = __ldg(&g_pre2[(size_t)jr*64 + 32 + lane]);
        }
#pragma unroll
        for (int r = 0; r < 16; r++) {
            float dxr = __shfl_sync(FULLMASK, dx, r);
            float dyr = __shfl_sync(FULLMASK, dy, r);
            float dzr = __shfl_sync(FULLMASK, dz, r);
            float v0 = pa0 + q0[r];
            v0 = fmaf(wc0x, dxr, v0); v0 = fmaf(wc0y, dyr, v0); v0 = fmaf(wc0z, dzr, v0);
            float v1 = pa1 + q1[r];
            v1 = fmaf(wc1x, dxr, v1); v1 = fmaf(wc1y, dyr, v1); v1 = fmaf(wc1z, dzr, v1);
            v0 = v0 >= 0.f ? v0 : 0.1f*v0;
            v1 = v1 >= 0.f ? v1 : 0.1f*v1;
            buf[w][r][lane]      = v0;
            buf[w][r][lane + 32] = v1;
        }
        __syncwarp();
        float o0[16], o1[16];
#pragma unroll
        for (int r = 0; r < 16; r++) { o0[r] = b1a; o1[r] = b1b; }
#pragma unroll 2
        for (int c4 = 0; c4 < 16; c4++) {
            float4 wa = *(const float4*)&w1s[lane*68 + c4*4];
            float4 wb = *(const float4*)&w1s[(lane+32)*68 + c4*4];
#pragma unroll
            for (int r = 0; r < 16; r++) {
                float4 f = *(const float4*)&buf[w][r][c4*4];
                o0[r] = fmaf(wa.x, f.x, o0[r]); o0[r] = fmaf(wa.y, f.y, o0[r]);
                o0[r] = fmaf(wa.z, f.z, o0[r]); o0[r] = fmaf(wa.w, f.w, o0[r]);
                o1[r] = fmaf(wb.x, f.x, o1[r]); o1[r] = fmaf(wb.y, f.y, o1[r]);
                o1[r] = fmaf(wb.z, f.z, o1[r]); o1[r] = fmaf(wb.w, f.w, o1[r]);
            }
        }
        float* dst = a ? g_featw : g_feat;
        size_t r2 = (size_t)i*16;
#pragma unroll
        for (int r = 0; r < 16; r++) {
            float v0 = o0[r] >= 0.f ? o0[r] : 0.1f*o0[r];
            float v1 = o1[r] >= 0.f ? o1[r] : 0.1f*o1[r];
            dst[(r2 + r)*64 + lane]      = v0;
            dst[(r2 + r)*64 + 32 + lane] = v1;
        }
        __syncwarp();
    }
}

// ---------------- wqk v4: 512 threads, thread = (c, k-pair), coalesced stores ----------------
__global__ __launch_bounds__(512) void wqk_k() {
    __shared__ __align__(16) float sf[64][68];   // 4n x 16k rows of feat,  64 c each
    __shared__ __align__(16) float sw[64][68];   // 4n x 16l rows of featw
    int ns = blockIdx.x;                // 0..NSPLIT-1 (64 n each)
    int b  = blockIdx.y;
    int tid = threadIdx.x;
    int c  = tid & 63;                  // channel
    int kp = tid >> 6;                  // k-pair 0..7

    float acc[2][16];
#pragma unroll
    for (int r = 0; r < 2; r++)
#pragma unroll
        for (int l = 0; l < 16; l++) acc[r][l] = 0.f;

    for (int ch = 0; ch < 16; ch++) {            // chunks of 4 n
        int n0 = ns*64 + ch*4;
        size_t rowbase = ((size_t)(b*NN + n0))*16;   // first (n,k) row
        __syncthreads();
#pragma unroll
        for (int v = 0; v < 2; v++) {
            int idx = v*512 + tid;               // 0..1023
            int row = idx >> 4, cf = (idx & 15)*4;
            *(float4*)&sf[row][cf] = *(const float4*)&g_feat [(rowbase + row)*64 + cf];
            *(float4*)&sw[row][cf] = *(const float4*)&g_featw[(rowbase + row)*64 + cf];
        }
        __syncthreads();
#pragma unroll
        for (int n = 0; n < 4; n++) {
            float wreg[16];
#pragma unroll
            for (int l = 0; l < 16; l++) wreg[l] = sw[n*16 + l][c];
            float fr[2];
#pragma unroll
            for (int r = 0; r < 2; r++) fr[r] = sf[n*16 + kp*2 + r][c];
#pragma unroll
            for (int r = 0; r < 2; r++)
#pragma unroll
                for (int l = 0; l < 16; l++)
                    acc[r][l] = fmaf(fr[r], wreg[l], acc[r][l]);
        }
    }
    size_t obase = ((size_t)(ns*BB + b))*256*64;     // [sp][b][kl][c]
#pragma unroll
    for (int r = 0; r < 2; r++)
#pragma unroll
        for (int l = 0; l < 16; l++)
            g_wqkp[obase + (size_t)((kp*2 + r)*16 + l)*64 + c] = acc[r][l];
}

// ---------------- softmax + clip + row/col sums ----------------
__global__ void softmax_k() {
    int t = blockIdx.x*256 + threadIdx.x;     // <<<8,256>>> -> 2048 threads
    int k  = t & 15;
    int bc = t >> 4;                          // 0..127 = b*64+c
    if (bc >= BB*CMX) return;
    int b = bc >> 6, c = bc & 63;
    const float inv_sqrt3 = 0.57735026918962576f;
    float row[16];
#pragma unroll
    for (int l = 0; l < 16; l++) {
        float s = 0.f;
        for (int sp = 0; sp < NSPLIT; sp++)
            s += g_wqkp[((size_t)(sp*BB + b)*256 + k*16 + l)*64 + c];
        row[l] = s;
    }
    float m = row[0];
#pragma unroll
    for (int l = 1; l < 16; l++) m = fmaxf(m, row[l]);
    float sum = 0.f;
#pragma unroll
    for (int l = 0; l < 16; l++) { row[l] = expf(row[l] - m); sum += row[l]; }
    float inv = 1.f / sum;
    float rs = 0.f;
#pragma unroll
    for (int l = 0; l < 16; l++) {
        float v = fmaxf(row[l]*inv*inv_sqrt3, 1e-10f);
        rs += v; row[l] = v;
    }
    g_rsum[bc*16 + k] = rs;
#pragma unroll
    for (int l = 0; l < 16; l++) {
        float v = row[l];
        v += __shfl_xor_sync(0xffffffffu, v, 1);
        v += __shfl_xor_sync(0xffffffffu, v, 2);
        v += __shfl_xor_sync(0xffffffffu, v, 4);
        v += __shfl_xor_sync(0xffffffffu, v, 8);
        if (k == 0) g_csum[bc*16 + l] = v;
    }
}

// ---------------- cost/costw: [b,n,c] layout for coalesced gather later ----------------
__global__ __launch_bounds__(256) void cost_k() {
    int t = blockIdx.x*256 + threadIdx.x;    // BN*64 threads
    int i = t >> 6, c = t & 63;
    int b = i >> 12;
    const float* cs = &g_csum[(size_t)(b*64 + c)*16];
    const float* rs = &g_rsum[(size_t)(b*64 + c)*16];
    float a = 0.f, aw = 0.f;
#pragma unroll
    for (int l = 0; l < 16; l++) {
        a  = fmaf(g_feat [((size_t)i*16 + l)*64 + c], cs[l], a);
        aw = fmaf(g_featw[((size_t)i*16 + l)*64 + c], rs[l], aw);
    }
    g_cost[t] = a; g_costw[t] = aw;
}

// ---------------- WeightNet + gather + final contraction ----------------
__global__ __launch_bounds__(128) void final_k(
    const float* __restrict__ wW0, const float* __restrict__ wb0,
    const float* __restrict__ wg0, const float* __restrict__ wbe0,
    const float* __restrict__ wW1, const float* __restrict__ wb1,
    const float* __restrict__ wg1, const float* __restrict__ wbe1,
    const float* __restrict__ wW2, const float* __restrict__ wb2,
    const float* __restrict__ wg2, const float* __restrict__ wbe2,
    float* __restrict__ out) {
    __shared__ float grp[128*65];           // grouped rows, padded
    __shared__ float w0f[24], b0f[8], s0f[8], e0f[8];
    __shared__ float w1f[64], b1f[8], s1f[8], e1f[8];
    __shared__ float w2f[512], b2f[64], s2f[64], e2f[64];
    int tid = threadIdx.x;
    const float invs = 1.f / sqrtf(1.f + 1e-5f);
    if (tid < 24) w0f[tid] = wW0[tid];
    if (tid < 8) {
        b0f[tid] = wb0[tid]; s0f[tid] = wg0[tid]*invs; e0f[tid] = wbe0[tid];
        b1f[tid] = wb1[tid]; s1f[tid] = wg1[tid]*invs; e1f[tid] = wbe1[tid];
    }
    if (tid < 64) {
        w1f[tid] = wW1[tid];
        b2f[tid] = wb2[tid]; s2f[tid] = wg2[tid]*invs; e2f[tid] = wbe2[tid];
    }
    for (int t = tid; t < 512; t += 128) w2f[t] = wW2[t];

    int i0 = blockIdx.x * 8;
    int b = i0 >> 12;
    __syncthreads();
    for (int s = 0; s < 64; s++) {
        int e = s*128 + tid;
        int rowe = e >> 6, ce = e & 63;
        int ie = i0 + (rowe >> 4);
        int ke = rowe & 15;
        int je = g_idxS[ie*16 + ke];
        int jg = (b << 12) + je;
        grp[rowe*65 + ce] = g_cost[(size_t)jg*64 + ce] + g_costw[(size_t)jg*64 + ce];
    }
    __syncthreads();

    int nl = tid >> 4, k = tid & 15;
    int i = i0 + nl, n = i & (NN - 1);
    int j = g_idxS[i*16 + k];
    int jg = (b << 12) + j;
    float4 Pj = g_p1[jg], Pi = g_p1[i];
    float dx = Pj.x - Pi.x, dy = Pj.y - Pi.y, dz = Pj.z - Pi.z;
    float h0[8];
#pragma unroll
    for (int o = 0; o < 8; o++) {
        float z = b0f[o] + w0f[o*3]*dx + w0f[o*3+1]*dy + w0f[o*3+2]*dz;
        z = z*s0f[o] + e0f[o];
        h0[o] = fmaxf(z, 0.f);
    }
    float h1[8];
#pragma unroll
    for (int o = 0; o < 8; o++) {
        float z = b1f[o];
#pragma unroll
        for (int c = 0; c < 8; c++) z = fmaf(w1f[o*8 + c], h0[c], z);
        z = z*s1f[o] + e1f[o];
        h1[o] = fmaxf(z, 0.f);
    }
    int myrow = nl*16 + k;
    for (int c = 0; c < 64; c++) {
        float z = b2f[c];
#pragma unroll
        for (int o = 0; o < 8; o++) z = fmaf(w2f[c*8 + o], h1[o], z);
        z = fmaxf(z*s2f[c] + e2f[c], 0.f);
        float v = z * grp[myrow*65 + c];
        v += __shfl_xor_sync(0xffffffffu, v, 1);
        v += __shfl_xor_sync(0xffffffffu, v, 2);
        v += __shfl_xor_sync(0xffffffffu, v, 4);
        v += __shfl_xor_sync(0xffffffffu, v, 8);
        if (k == 0) out[((size_t)b*CMX + c)*NN + n] = v;
    }
}

// ---------------- launch ----------------
extern "C" void kernel_launch(void* const* d_in, const int* in_sizes, int n_in,
                              void* d_out, int out_size) {
    const float* xyz1    = (const float*)d_in[0];
    const float* xyz2    = (const float*)d_in[1];
    const float* xyz2w   = (const float*)d_in[2];
    const float* points1 = (const float*)d_in[3];
    const float* points2 = (const float*)d_in[4];
    const float* mlp_W0  = (const float*)d_in[5];
    const float* mlp_b0  = (const float*)d_in[6];
    const float* mlp_W1  = (const float*)d_in[7];
    const float* mlp_b1  = (const float*)d_in[8];
    const float* wn_W0   = (const float*)d_in[9];
    const float* wn_b0   = (const float*)d_in[10];
    const float* wn_g0   = (const float*)d_in[11];
    const float* wn_be0  = (const float*)d_in[12];
    const float* wn_W1   = (const float*)d_in[13];
    const float* wn_b1   = (const float*)d_in[14];
    const float* wn_g1   = (const float*)d_in[15];
    const float* wn_be1  = (const float*)d_in[16];
    const float* wn_W2   = (const float*)d_in[17];
    const float* wn_b2   = (const float*)d_in[18];
    const float* wn_g2   = (const float*)d_in[19];
    const float* wn_be2  = (const float*)d_in[20];
    float* out = (float*)d_out;

    prep_k<<<dim3(NN/32, DD/32, 5), dim3(32, 8)>>>(points1, points2, xyz1, xyz2, xyz2w);
    knn3_part1_k<<<dim3(BN/8, 5), 256>>>(mlp_W0, mlp_b0);
    mlp_k<<<2048, 128>>>(mlp_W0, mlp_W1, mlp_b1);
    wqk_k<<<dim3(NSPLIT, BB), 512>>>();
    softmax_k<<<8, 256>>>();
    cost_k<<<BN*64/256, 256>>>();
    final_k<<<BN/8, 128>>>(wn_W0, wn_b0, wn_g0, wn_be0,
                           wn_W1, wn_b1, wn_g1, wn_be1,
                           wn_W2, wn_b2, wn_g2, wn_be2, out);
}